// round 11
// baseline (speedup 1.0000x reference)
#include <cuda_runtime.h>

#define N0 16
#define N1 200
#define N2 200
#define NPIX (N1*N2)          // 40000
#define NVOX (N0*NPIX)        // 640000
#define NPHI 190
#define NRAD 223
#define NT 351
#define GR 4                  // gaussian radius
#define NSLOT (NPHI*NRAD)     // 42370
#define NCH 8                 // phi chunks for backprojection
#define CHW 24                // ceil(190/8)
#define NTB 13                // 16x16 pixel tiles per axis (ceil(200/16))
#define MAXROWS 40            // smem row capacity (worst case ~31)

// ---------------- scratch (device globals; no allocation allowed) ----------
__device__ __align__(16) float d_GW[2*GR+1];
__device__ float d_COS[NPHI];
__device__ float d_SIN[NPHI];
__device__ float d_RV[NRAD];
__device__ __align__(16) float d_buf1[NVOX];
__device__ __align__(16) float d_st2[2*NVOX + 2*N0*N2];  // paired img + pad i-row
__device__ __align__(16) float d_zr[NSLOT*N0];           // mult*data/exp, [sidx][z]
__device__ __align__(16) float d_bp[NCH*NVOX];           // backprojection partials

// ---------------- packed f32x2 helpers (Blackwell) --------------------------
__device__ __forceinline__ unsigned long long f2_pack(float a, float b)
{
    unsigned long long r;
    asm("mov.b64 %0, {%1,%2};" : "=l"(r) : "f"(a), "f"(b));
    return r;
}
__device__ __forceinline__ void f2_fma(unsigned long long& d,
                                       unsigned long long a, unsigned long long b)
{
    asm("fma.rn.f32x2 %0, %1, %2, %0;" : "+l"(d) : "l"(a), "l"(b));
}
__device__ __forceinline__ unsigned long long f2_add(unsigned long long a,
                                                     unsigned long long b)
{
    unsigned long long r;
    asm("add.rn.f32x2 %0, %1, %2;" : "=l"(r) : "l"(a), "l"(b));
    return r;
}
__device__ __forceinline__ float2 f2_unpack(unsigned long long v)
{
    float2 r;
    asm("mov.b64 {%0,%1}, %2;" : "=f"(r.x), "=f"(r.y) : "l"(v));
    return r;
}

// ---------------- constant tables (match numpy float64 -> float32) ---------
__global__ void k_init()
{
    int t = blockIdx.x * blockDim.x + threadIdx.x;
    if (t == 0) {
        const double sigma = 4.5 / (2.35 * 2.0);
        double g[2*GR+1];
        double sum = 0.0;
        for (int k = 0; k <= 2*GR; k++) {
            double d = (double)(k - GR) / sigma;
            g[k] = exp(-0.5 * d * d);
            sum += g[k];
        }
        for (int k = 0; k <= 2*GR; k++) d_GW[k] = (float)(g[k] / sum);
    }
    const double PI = 3.14159265358979323846;
    for (int i = t; i < NPHI; i += blockDim.x * gridDim.x) {
        float phi = (float)((double)i * (PI / 190.0));   // linspace f64 -> f32
        d_COS[i] = (float)cos((double)phi);
        d_SIN[i] = (float)sin((double)phi);
    }
    for (int i = t; i < NRAD; i += blockDim.x * gridDim.x) {
        d_RV[i] = (float)(-200.0 + (double)i * (400.0 / 222.0));
    }
}

__device__ __forceinline__ int refl(int m, int n)
{
    if (m < 0)  m = -1 - m;
    if (m >= n) m = 2*n - 1 - m;
    return m;
}

// ---------------- fused forward gauss3 + paired z-transpose -----------------
__global__ void k_gauss3t2(const float* __restrict__ in, float* __restrict__ out2)
{
    __shared__ float ta[N0][N2 + 1];
    __shared__ float tb[N0][N2 + 1];
    int i = blockIdx.x;
    int ridx[2*GR+1];
    #pragma unroll
    for (int d = -GR; d <= GR; d++) ridx[d+GR] = refl(i + d, N1);
    // phase 1: i-smooth
    for (int t = threadIdx.x; t < N0*N2; t += blockDim.x) {
        int j = t % N2;
        int z = t / N2;
        const float* base = in + z*NPIX + j;
        float s = 0.f;
        #pragma unroll
        for (int d = 0; d < 2*GR+1; d++)
            s += d_GW[d] * base[ridx[d]*N2];
        ta[z][j] = s;
    }
    __syncthreads();
    // phase 2: j-smooth (ta -> tb)
    for (int t = threadIdx.x; t < N0*N2; t += blockDim.x) {
        int j = t % N2;
        int z = t / N2;
        float s = 0.f;
        if (j >= GR && j < N2-GR) {
            #pragma unroll
            for (int d = -GR; d <= GR; d++)
                s += d_GW[d+GR] * ta[z][j+d];
        } else {
            #pragma unroll
            for (int d = -GR; d <= GR; d++)
                s += d_GW[d+GR] * ta[z][refl(j+d, N2)];
        }
        tb[z][j] = s;
    }
    __syncthreads();
    // phase 3: z-smooth (tb -> ta)
    for (int t = threadIdx.x; t < N0*N2; t += blockDim.x) {
        int j = t % N2;
        int z = t / N2;
        float s = 0.f;
        #pragma unroll
        for (int d = -GR; d <= GR; d++) {
            int m = z + d;
            if (m < 0)   m = -1 - m;
            if (m >= N0) m = 2*N0 - 1 - m;
            s += d_GW[d+GR] * tb[m][j];
        }
        ta[z][j] = s;
    }
    __syncthreads();
    // phase 4: paired-z writes
    for (int t = threadIdx.x; t < N0*N2; t += blockDim.x) {
        int z = t & (N0-1);
        int j = t >> 4;
        int j1 = min(j + 1, N2 - 1);
        float v0 = ta[z][j];
        float v1 = ta[z][j1];
        unsigned base = ((unsigned)(i*N2 + j)) << 5;
        out2[base + z]      = v0;
        out2[base + N0 + z] = v1;
        if (i == N1-1) {   // pad row i = N1 duplicates i = N1-1
            unsigned pbase = ((unsigned)(N1*N2 + j)) << 5;
            out2[pbase + z]      = v0;
            out2[pbase + N0 + z] = v1;
        }
    }
}

// ---------------- forward projection + ratio (fused) ------------------------
__global__ void k_project(const float* __restrict__ st2,
                          const float* __restrict__ data,
                          const float* __restrict__ contam,
                          const float* __restrict__ mult,
                          float* __restrict__ zr)
{
    int t = blockIdx.x * blockDim.x + threadIdx.x;
    int lane8 = t & 7;
    int ray   = t >> 3;
    bool live = (ray < NSLOT);
    if (!live) ray = NSLOT - 1;           // clamp: keep all 32 lanes for shfl
    int phi = ray / NRAD;
    int rad = ray - phi * NRAD;
    int zq  = lane8 & 3;
    bool isj1 = lane8 >= 4;
    float wjb = isj1 ? 0.f : 1.f;         // wj = fma(fj, wjs, wjb)
    float wjs = isj1 ? 1.f : -1.f;

    float c = d_COS[phi], s = d_SIN[phi];
    float r = d_RV[rad];
    float rns = r * (-s);
    float rc  = r * c;

    float A = 0.5f * (rns + 199.f) - 175.f * c;
    float B = 0.5f * (rc  + 199.f) - 175.f * s;

    const float EPS = 1e-6f;
    float lo = 0.f, hi = 350.f;
    bool empty = false;
    if (fabsf(c) > EPS) {
        float n0 = (0.f   - A) / c;
        float n1 = (199.f - A) / c;
        lo = fmaxf(lo, fminf(n0, n1)); hi = fminf(hi, fmaxf(n0, n1));
    } else if (A < 0.f || A > 199.f) empty = true;
    if (fabsf(s) > EPS) {
        float n0 = (0.f   - B) / s;
        float n1 = (199.f - B) / s;
        lo = fmaxf(lo, fminf(n0, n1)); hi = fminf(hi, fmaxf(n0, n1));
    } else if (B < 0.f || B > 199.f) empty = true;

    unsigned long long acc01 = 0ull, acc23 = 0ull;
    if (!empty && hi >= lo) {
        int nlo = max(0,    (int)floorf(lo) - 1);
        int nhi = min(NT-1, (int)ceilf (hi) + 1);
        float hc = 0.5f * c, hs = 0.5f * s;
        float Kx = 0.5f * (rns + 199.f);
        float Ky = 0.5f * (rc  + 199.f);

        // trim to the exact valid contiguous interval (same fp formula)
        while (nlo <= nhi) {
            float tn = -350.f + 2.f * (float)nlo;
            float ix = __fmaf_rn(tn, hc, Kx);
            float iy = __fmaf_rn(tn, hs, Ky);
            if (ix >= 0.f && ix <= 199.f && iy >= 0.f && iy <= 199.f) break;
            nlo++;
        }
        while (nhi >= nlo) {
            float tn = -350.f + 2.f * (float)nhi;
            float ix = __fmaf_rn(tn, hc, Kx);
            float iy = __fmaf_rn(tn, hs, Ky);
            if (ix >= 0.f && ix <= 199.f && iy >= 0.f && iy <= 199.f) break;
            nhi--;
        }

        float tn = -350.f + 2.f * (float)nlo;
        for (int n = nlo; n <= nhi; n++, tn += 2.f) {
            float ix = __fmaf_rn(tn, hc, Kx);
            float iy = __fmaf_rn(tn, hs, Ky);
            int i0 = (int)ix;
            int j0 = (int)iy;
            float fi = ix - (float)i0;
            float fj = iy - (float)j0;
            float wj = __fmaf_rn(fj, wjs, wjb);
            unsigned base = ((unsigned)(i0*N2 + j0)) << 5;
            const unsigned iofs = (unsigned)(N2*2*N0);            // pad row
            ulonglong2 q0 = *((const ulonglong2*)(st2 + base) + lane8);
            ulonglong2 q1 = *((const ulonglong2*)(st2 + base + iofs) + lane8);
            float w0 = wj * (1.f - fi);
            float w1 = wj * fi;
            unsigned long long w0p = f2_pack(w0, w0);
            unsigned long long w1p = f2_pack(w1, w1);
            f2_fma(acc01, w0p, q0.x);
            f2_fma(acc01, w1p, q1.x);
            f2_fma(acc23, w0p, q0.y);
            f2_fma(acc23, w1p, q1.y);
        }
    }

    acc01 = f2_add(acc01, __shfl_down_sync(0xffffffffu, acc01, 4));
    acc23 = f2_add(acc23, __shfl_down_sync(0xffffffffu, acc23, 4));

    if (live && !isj1) {
        int sidx = ray;
        float2 u01 = f2_unpack(acc01);
        float2 u23 = f2_unpack(acc23);
        float pr[4] = { u01.x*2.f, u01.y*2.f, u23.x*2.f, u23.y*2.f };
        float4 o;
        float* ov = (float*)&o;
        #pragma unroll
        for (int k = 0; k < 4; k++) {
            int gi = (zq*4 + k) * NSLOT + sidx;
            float mm = mult[gi];
            float e  = __fmaf_rn(mm, pr[k], contam[gi]);
            ov[k] = mm * data[gi] / e;
        }
        ((float4*)zr)[sidx*4 + zq] = o;
    }
}

// ---------------- backprojection (smem-staged zr rows) ----------------------
// block = 16x16 pixel tile x one phi-chunk. Per phi, the block's union of zr
// rows is a contiguous m-interval (<= ~31 rows); stage it in smem coalesced,
// then threads gather from LDS. W math identical to round 9/10 (bit-exact).
__global__ void k_backproject(const float* __restrict__ zr, float* __restrict__ bp)
{
    __shared__ float srow[MAXROWS * N0];

    int ch  = blockIdx.z;
    int lane = threadIdx.x & 31;
    int w    = threadIdx.x >> 5;       // 8 warps: 2 in j, 4 in i
    int j = blockIdx.x*16 + (w & 1)*8 + (lane & 7);
    int i = blockIdx.y*16 + (w >> 1)*4 + (lane >> 3);
    bool valid = (i < N1) && (j < N2);
    if (i > N1-1) i = N1-1;            // clamp: duplicates edge pixel, no store
    if (j > N2-1) j = N2-1;

    // tile bounding box (clamped threads stay inside)
    int i0t = blockIdx.y*16,  i1t = min(i0t + 15, N1-1);
    int j0t = blockIdx.x*16,  j1t = min(j0t + 15, N2-1);
    float Xmin = -199.f + 2.f*(float)i0t, Xmax = -199.f + 2.f*(float)i1t;
    float Ymin = -199.f + 2.f*(float)j0t, Ymax = -199.f + 2.f*(float)j1t;

    float X = -199.f + 2.f * (float)i;
    float Y = -199.f + 2.f * (float)j;

    unsigned long long accp[8];
    #pragma unroll
    for (int k = 0; k < 8; k++) accp[k] = 0ull;

    const float inv_dr = (float)(222.0 / 400.0);
    float cx = 99.5f - (float)i;
    float cy = 99.5f - (float)j;
    float vxl = -(float)i,  vxh = 199.f - (float)i;
    float vyl = -(float)j,  vyh = 199.f - (float)j;
    bool interior = (i >= 1 && i <= N1-2 && j >= 1 && j <= N2-2);

    int plo = ch * CHW;
    int phi_end = min(NPHI, plo + CHW);

    for (int phi = plo; phi < phi_end; phi++) {
        float c = d_COS[phi], s = d_SIN[phi];   // s >= 0 on [0, pi)
        float lim = 2.f * (fabsf(c) + fabsf(s)) + 1e-2f;

        // block-level m bounds from tile corners (same monotone fp ops as the
        // per-pixel formula below, +-1 row safety margin)
        float yc_min = (c >= 0.f) ? Ymin*c : Ymax*c;
        float yc_max = (c >= 0.f) ? Ymax*c : Ymin*c;
        float r0min = __fmaf_rn(-Xmax, s, yc_min);
        float r0max = __fmaf_rn(-Xmin, s, yc_max);
        int mloB = max(0,      (int)ceilf ((r0min + 200.f - lim) * inv_dr) - 1);
        int mhiB = min(NRAD-1, (int)floorf((r0max + 200.f + lim) * inv_dr) + 1);
        int nrows = mhiB - mloB + 1;
        if (nrows > MAXROWS) nrows = MAXROWS;    // unreachable by construction

        __syncthreads();
        if (nrows > 0) {
            const float* src = zr + (phi*NRAD + mloB)*N0;
            for (int k = threadIdx.x; k < nrows*N0; k += 256)
                srow[k] = src[k];
        }
        __syncthreads();
        if (nrows <= 0) continue;                // uniform across block

        float r0 = __fmaf_rn(-X, s, Y*c);
        float t0 =  X*c + Y*s;
        int mlo = max(mloB, (int)ceilf ((r0 + 200.f - lim) * inv_dr));
        int mhi = min(mhiB, (int)floorf((r0 + 200.f + lim) * inv_dr));
        int nlo = max(0,    (int)ceilf ((t0 + 350.f - lim) * 0.5f));
        int nhi = min(NT-1, (int)floorf((t0 + 350.f + lim) * 0.5f));
        int ncnt = nhi - nlo;
        if (ncnt < 0 || mhi < mlo) continue;

        float hc = 0.5f * c, hs = 0.5f * s;
        float tn0 = -350.f + 2.f * (float)nlo;

        for (int m = mlo; m <= mhi; m++) {
            float rm = d_RV[m];
            float Kx = __fmaf_rn(rm, -hs, cx);
            float Ky = __fmaf_rn(rm,  hc, cy);
            float W = 0.f;
            if (interior) {
                float tn = tn0;
                for (int n = 0; n <= ncnt; n++, tn += 2.f) {
                    float dx = __fmaf_rn(tn, hc, Kx);
                    float dy = __fmaf_rn(tn, hs, Ky);
                    float wx = fmaxf(1.f - fabsf(dx), 0.f);
                    float wy = fmaxf(1.f - fabsf(dy), 0.f);
                    W = __fmaf_rn(wx, wy, W);
                }
            } else {
                float tn = tn0;
                for (int n = 0; n <= ncnt; n++, tn += 2.f) {
                    float dx = __fmaf_rn(tn, hc, Kx);
                    float dy = __fmaf_rn(tn, hs, Ky);
                    if (dx < vxl || dx > vxh || dy < vyl || dy > vyh) continue;
                    float wx = fmaxf(1.f - fabsf(dx), 0.f);
                    float wy = fmaxf(1.f - fabsf(dy), 0.f);
                    W = __fmaf_rn(wx, wy, W);
                }
            }
            if (W != 0.f) {
                const ulonglong2* zp = (const ulonglong2*)(srow + (m - mloB)*N0);
                ulonglong2 p0 = zp[0], p1 = zp[1], p2 = zp[2], p3 = zp[3];
                unsigned long long Wp = f2_pack(W, W);
                f2_fma(accp[0], Wp, p0.x);
                f2_fma(accp[1], Wp, p0.y);
                f2_fma(accp[2], Wp, p1.x);
                f2_fma(accp[3], Wp, p1.y);
                f2_fma(accp[4], Wp, p2.x);
                f2_fma(accp[5], Wp, p2.y);
                f2_fma(accp[6], Wp, p3.x);
                f2_fma(accp[7], Wp, p3.y);
            }
        }
    }
    if (valid) {
        float* dst = bp + ch * NVOX;
        int pix = i * N2 + j;
        #pragma unroll
        for (int k = 0; k < 8; k++) {
            float2 u2 = f2_unpack(accp[k]);
            dst[(2*k  )*NPIX + pix] = u2.x * 2.f;   // * STEP
            dst[(2*k+1)*NPIX + pix] = u2.y * 2.f;
        }
    }
}

// ---------------- adjoint gauss: fused combine + j-smooth + z-smooth --------
__global__ void k_smooth_jz(const float* __restrict__ bp, float* __restrict__ out)
{
    __shared__ float ta[N0][N2 + 1];
    __shared__ float tj[N0][N2 + 1];
    int i = blockIdx.x;
    // phase 0: combine NCH backprojection partials
    for (int t = threadIdx.x; t < N0*N2; t += blockDim.x) {
        int j = t % N2;
        int z = t / N2;
        const float* base = bp + z*NPIX + i*N2 + j;
        float s = 0.f;
        #pragma unroll
        for (int ch = 0; ch < NCH; ch++)
            s += base[ch*NVOX];
        ta[z][j] = s;
    }
    __syncthreads();
    // phase 1: j-smooth (ta -> tj)
    for (int t = threadIdx.x; t < N0*N2; t += blockDim.x) {
        int j = t % N2;
        int z = t / N2;
        float s = 0.f;
        if (j >= GR && j < N2-GR) {
            #pragma unroll
            for (int d = -GR; d <= GR; d++)
                s += d_GW[d+GR] * ta[z][j+d];
        } else {
            #pragma unroll
            for (int d = -GR; d <= GR; d++)
                s += d_GW[d+GR] * ta[z][refl(j+d, N2)];
        }
        tj[z][j] = s;
    }
    __syncthreads();
    // phase 2: z-smooth -> global
    for (int t = threadIdx.x; t < N0*N2; t += blockDim.x) {
        int j = t % N2;
        int z = t / N2;
        float s = 0.f;
        #pragma unroll
        for (int d = -GR; d <= GR; d++) {
            int m = z + d;
            if (m < 0)   m = -1 - m;
            if (m >= N0) m = 2*N0 - 1 - m;
            s += d_GW[d+GR] * tj[m][j];
        }
        out[z*NPIX + i*N2 + j] = s;
    }
}

// ---------------- adjoint i-smooth + MLEM update -----------------------------
__global__ void k_smooth_i_final(const float* __restrict__ gin,
                                 const float* __restrict__ x,
                                 const float* __restrict__ sens,
                                 float* __restrict__ out)
{
    int t = blockIdx.x * blockDim.x + threadIdx.x;
    if (t >= NVOX) return;
    int j = t % N2;
    int i = (t / N2) % N1;
    int z = t / NPIX;
    const float* base = gin + z*NPIX + j;
    float s = 0.f;
    if (i >= GR && i < N1-GR) {
        #pragma unroll
        for (int d = -GR; d <= GR; d++)
            s += d_GW[d+GR] * base[(i+d) * N2];
    } else {
        #pragma unroll
        for (int d = -GR; d <= GR; d++)
            s += d_GW[d+GR] * base[refl(i+d, N1) * N2];
    }
    out[t] = x[t] * s / sens[t];
}

// ---------------- launch ----------------------------------------------------
extern "C" void kernel_launch(void* const* d_in, const int* in_sizes, int n_in,
                              void* d_out, int out_size)
{
    const float* x      = (const float*)d_in[0];
    const float* data   = (const float*)d_in[1];
    const float* contam = (const float*)d_in[2];
    const float* mult   = (const float*)d_in[3];
    const float* sens   = (const float*)d_in[4];
    float* out = (float*)d_out;

    float *buf1, *st2, *zr, *bp;
    cudaGetSymbolAddress((void**)&buf1, d_buf1);
    cudaGetSymbolAddress((void**)&st2,  d_st2);
    cudaGetSymbolAddress((void**)&zr,   d_zr);
    cudaGetSymbolAddress((void**)&bp,   d_bp);

    k_init<<<1, 256>>>();

    // forward: fused gauss3 + paired transposed image
    k_gauss3t2<<<N1, 512>>>(x, st2);

    // project + exp + ratio (fused, 8 lanes/ray, checkless hot loop)
    k_project<<<(NSLOT*8 + 255)/256, 256>>>(st2, data, contam, mult, zr);

    // adjoint: backproject (smem-staged), fused combine+j+z smooth, i-smooth+MLEM
    dim3 bgrid(NTB, NTB, NCH);
    k_backproject<<<bgrid, 256>>>(zr, bp);
    k_smooth_jz<<<N1, 512>>>(bp, buf1);
    k_smooth_i_final<<<(NVOX + 255)/256, 256>>>(buf1, x, sens, out);
}

// round 12
// speedup vs baseline: 1.0845x; 1.0845x over previous
#include <cuda_runtime.h>

#define N0 16
#define N1 200
#define N2 200
#define NPIX (N1*N2)          // 40000
#define NVOX (N0*NPIX)        // 640000
#define NPHI 190
#define NRAD 223
#define NT 351
#define GR 4                  // gaussian radius
#define NSLOT (NPHI*NRAD)     // 42370
#define NCH 8                 // phi chunks for backprojection
#define CHW 24                // ceil(190/8)

// ---------------- scratch (device globals; no allocation allowed) ----------
__device__ __align__(16) float d_GW[2*GR+1];
__device__ float d_COS[NPHI];
__device__ float d_SIN[NPHI];
__device__ float d_RV[NRAD];
__device__ __align__(16) float d_buf1[NVOX];
__device__ __align__(16) float d_st2[2*NVOX + 2*N0*N2];  // paired img + pad i-row
__device__ __align__(16) float d_zr[NSLOT*N0];           // mult*data/exp, [sidx][z]
__device__ __align__(16) float d_bp[NCH*NVOX];           // backprojection partials

// ---------------- packed f32x2 helpers (Blackwell) --------------------------
__device__ __forceinline__ unsigned long long f2_pack(float a, float b)
{
    unsigned long long r;
    asm("mov.b64 %0, {%1,%2};" : "=l"(r) : "f"(a), "f"(b));
    return r;
}
__device__ __forceinline__ void f2_fma(unsigned long long& d,
                                       unsigned long long a, unsigned long long b)
{
    asm("fma.rn.f32x2 %0, %1, %2, %0;" : "+l"(d) : "l"(a), "l"(b));
}
__device__ __forceinline__ unsigned long long f2_add(unsigned long long a,
                                                     unsigned long long b)
{
    unsigned long long r;
    asm("add.rn.f32x2 %0, %1, %2;" : "=l"(r) : "l"(a), "l"(b));
    return r;
}
__device__ __forceinline__ float2 f2_unpack(unsigned long long v)
{
    float2 r;
    asm("mov.b64 {%0,%1}, %2;" : "=f"(r.x), "=f"(r.y) : "l"(v));
    return r;
}

// ---------------- constant tables (match numpy float64 -> float32) ---------
__global__ void k_init()
{
    int t = blockIdx.x * blockDim.x + threadIdx.x;
    if (t == 0) {
        const double sigma = 4.5 / (2.35 * 2.0);
        double g[2*GR+1];
        double sum = 0.0;
        for (int k = 0; k <= 2*GR; k++) {
            double d = (double)(k - GR) / sigma;
            g[k] = exp(-0.5 * d * d);
            sum += g[k];
        }
        for (int k = 0; k <= 2*GR; k++) d_GW[k] = (float)(g[k] / sum);
    }
    const double PI = 3.14159265358979323846;
    for (int i = t; i < NPHI; i += blockDim.x * gridDim.x) {
        float phi = (float)((double)i * (PI / 190.0));   // linspace f64 -> f32
        d_COS[i] = (float)cos((double)phi);
        d_SIN[i] = (float)sin((double)phi);
    }
    for (int i = t; i < NRAD; i += blockDim.x * gridDim.x) {
        d_RV[i] = (float)(-200.0 + (double)i * (400.0 / 222.0));
    }
}

__device__ __forceinline__ int refl(int m, int n)
{
    if (m < 0)  m = -1 - m;
    if (m >= n) m = 2*n - 1 - m;
    return m;
}

// ---------------- fused forward gauss3 + paired z-transpose -----------------
__global__ void k_gauss3t2(const float* __restrict__ in, float* __restrict__ out2)
{
    __shared__ float ta[N0][N2 + 1];
    __shared__ float tb[N0][N2 + 1];
    int i = blockIdx.x;
    int ridx[2*GR+1];
    #pragma unroll
    for (int d = -GR; d <= GR; d++) ridx[d+GR] = refl(i + d, N1);
    // phase 1: i-smooth
    for (int t = threadIdx.x; t < N0*N2; t += blockDim.x) {
        int j = t % N2;
        int z = t / N2;
        const float* base = in + z*NPIX + j;
        float s = 0.f;
        #pragma unroll
        for (int d = 0; d < 2*GR+1; d++)
            s += d_GW[d] * base[ridx[d]*N2];
        ta[z][j] = s;
    }
    __syncthreads();
    // phase 2: j-smooth (ta -> tb)
    for (int t = threadIdx.x; t < N0*N2; t += blockDim.x) {
        int j = t % N2;
        int z = t / N2;
        float s = 0.f;
        if (j >= GR && j < N2-GR) {
            #pragma unroll
            for (int d = -GR; d <= GR; d++)
                s += d_GW[d+GR] * ta[z][j+d];
        } else {
            #pragma unroll
            for (int d = -GR; d <= GR; d++)
                s += d_GW[d+GR] * ta[z][refl(j+d, N2)];
        }
        tb[z][j] = s;
    }
    __syncthreads();
    // phase 3: z-smooth (tb -> ta)
    for (int t = threadIdx.x; t < N0*N2; t += blockDim.x) {
        int j = t % N2;
        int z = t / N2;
        float s = 0.f;
        #pragma unroll
        for (int d = -GR; d <= GR; d++) {
            int m = z + d;
            if (m < 0)   m = -1 - m;
            if (m >= N0) m = 2*N0 - 1 - m;
            s += d_GW[d+GR] * tb[m][j];
        }
        ta[z][j] = s;
    }
    __syncthreads();
    // phase 4: paired-z writes
    for (int t = threadIdx.x; t < N0*N2; t += blockDim.x) {
        int z = t & (N0-1);
        int j = t >> 4;
        int j1 = min(j + 1, N2 - 1);
        float v0 = ta[z][j];
        float v1 = ta[z][j1];
        unsigned base = ((unsigned)(i*N2 + j)) << 5;
        out2[base + z]      = v0;
        out2[base + N0 + z] = v1;
        if (i == N1-1) {   // pad row i = N1 duplicates i = N1-1
            unsigned pbase = ((unsigned)(N1*N2 + j)) << 5;
            out2[pbase + z]      = v0;
            out2[pbase + N0 + z] = v1;
        }
    }
}

// ---------------- forward projection + ratio (fused) ------------------------
__global__ void k_project(const float* __restrict__ st2,
                          const float* __restrict__ data,
                          const float* __restrict__ contam,
                          const float* __restrict__ mult,
                          float* __restrict__ zr)
{
    int t = blockIdx.x * blockDim.x + threadIdx.x;
    int lane8 = t & 7;
    int ray   = t >> 3;
    bool live = (ray < NSLOT);
    if (!live) ray = NSLOT - 1;           // clamp: keep all 32 lanes for shfl
    int phi = ray / NRAD;
    int rad = ray - phi * NRAD;
    int zq  = lane8 & 3;
    bool isj1 = lane8 >= 4;
    float wjb = isj1 ? 0.f : 1.f;         // wj = fma(fj, wjs, wjb)
    float wjs = isj1 ? 1.f : -1.f;

    float c = d_COS[phi], s = d_SIN[phi];
    float r = d_RV[rad];
    float rns = r * (-s);
    float rc  = r * c;

    float A = 0.5f * (rns + 199.f) - 175.f * c;
    float B = 0.5f * (rc  + 199.f) - 175.f * s;

    const float EPS = 1e-6f;
    float lo = 0.f, hi = 350.f;
    bool empty = false;
    if (fabsf(c) > EPS) {
        float n0 = (0.f   - A) / c;
        float n1 = (199.f - A) / c;
        lo = fmaxf(lo, fminf(n0, n1)); hi = fminf(hi, fmaxf(n0, n1));
    } else if (A < 0.f || A > 199.f) empty = true;
    if (fabsf(s) > EPS) {
        float n0 = (0.f   - B) / s;
        float n1 = (199.f - B) / s;
        lo = fmaxf(lo, fminf(n0, n1)); hi = fminf(hi, fmaxf(n0, n1));
    } else if (B < 0.f || B > 199.f) empty = true;

    unsigned long long acc01 = 0ull, acc23 = 0ull;
    if (!empty && hi >= lo) {
        int nlo = max(0,    (int)floorf(lo) - 1);
        int nhi = min(NT-1, (int)ceilf (hi) + 1);
        float hc = 0.5f * c, hs = 0.5f * s;
        float Kx = 0.5f * (rns + 199.f);
        float Ky = 0.5f * (rc  + 199.f);

        // trim to the exact valid contiguous interval (same fp formula)
        while (nlo <= nhi) {
            float tn = -350.f + 2.f * (float)nlo;
            float ix = __fmaf_rn(tn, hc, Kx);
            float iy = __fmaf_rn(tn, hs, Ky);
            if (ix >= 0.f && ix <= 199.f && iy >= 0.f && iy <= 199.f) break;
            nlo++;
        }
        while (nhi >= nlo) {
            float tn = -350.f + 2.f * (float)nhi;
            float ix = __fmaf_rn(tn, hc, Kx);
            float iy = __fmaf_rn(tn, hs, Ky);
            if (ix >= 0.f && ix <= 199.f && iy >= 0.f && iy <= 199.f) break;
            nhi--;
        }

        float tn = -350.f + 2.f * (float)nlo;
        for (int n = nlo; n <= nhi; n++, tn += 2.f) {
            float ix = __fmaf_rn(tn, hc, Kx);
            float iy = __fmaf_rn(tn, hs, Ky);
            int i0 = (int)ix;
            int j0 = (int)iy;
            float fi = ix - (float)i0;
            float fj = iy - (float)j0;
            float wj = __fmaf_rn(fj, wjs, wjb);
            unsigned base = ((unsigned)(i0*N2 + j0)) << 5;
            const unsigned iofs = (unsigned)(N2*2*N0);            // pad row
            ulonglong2 q0 = *((const ulonglong2*)(st2 + base) + lane8);
            ulonglong2 q1 = *((const ulonglong2*)(st2 + base + iofs) + lane8);
            float w0 = wj * (1.f - fi);
            float w1 = wj * fi;
            unsigned long long w0p = f2_pack(w0, w0);
            unsigned long long w1p = f2_pack(w1, w1);
            f2_fma(acc01, w0p, q0.x);
            f2_fma(acc01, w1p, q1.x);
            f2_fma(acc23, w0p, q0.y);
            f2_fma(acc23, w1p, q1.y);
        }
    }

    acc01 = f2_add(acc01, __shfl_down_sync(0xffffffffu, acc01, 4));
    acc23 = f2_add(acc23, __shfl_down_sync(0xffffffffu, acc23, 4));

    if (live && !isj1) {
        int sidx = ray;
        float2 u01 = f2_unpack(acc01);
        float2 u23 = f2_unpack(acc23);
        float pr[4] = { u01.x*2.f, u01.y*2.f, u23.x*2.f, u23.y*2.f };
        float4 o;
        float* ov = (float*)&o;
        #pragma unroll
        for (int k = 0; k < 4; k++) {
            int gi = (zq*4 + k) * NSLOT + sidx;
            float mm = mult[gi];
            float e  = __fmaf_rn(mm, pr[k], contam[gi]);
            ov[k] = mm * data[gi] / e;
        }
        ((float4*)zr)[sidx*4 + zq] = o;
    }
}

// ---------------- backprojection (tiled-warp gather, round-10 body) ---------
// one thread = (pixel, phi-chunk); warp covers an 8j x 4i pixel tile.
// __launch_bounds__(256, 5): cap regs ~51 to lift occupancy 44% -> ~62%.
__global__ void __launch_bounds__(256, 5)
k_backproject(const float* __restrict__ zr, float* __restrict__ bp)
{
    int tid = blockIdx.x * blockDim.x + threadIdx.x;
    if (tid >= NCH * NPIX) return;
    int ch = tid / NPIX;
    int u  = tid % NPIX;                  // NPIX % 32 == 0: warps stay in-chunk
    int lane = u & 31;
    int wu   = u >> 5;                    // 0..1249
    int ti = wu / (N2/8);                 // 0..49  (i tile)
    int tj = wu % (N2/8);                 // 0..24  (j tile)
    int i = ti*4 + (lane >> 3);
    int j = tj*8 + (lane & 7);
    int pix = i * N2 + j;

    float X = -199.f + 2.f * (float)i;
    float Y = -199.f + 2.f * (float)j;

    unsigned long long accp[8];
    #pragma unroll
    for (int k = 0; k < 8; k++) accp[k] = 0ull;

    const float inv_dr = (float)(222.0 / 400.0);
    float cx = 99.5f - (float)i;
    float cy = 99.5f - (float)j;
    float vxl = -(float)i,  vxh = 199.f - (float)i;
    float vyl = -(float)j,  vyh = 199.f - (float)j;
    bool interior = (i >= 1 && i <= N1-2 && j >= 1 && j <= N2-2);

    int plo = ch * CHW;
    int phi_end = min(NPHI, plo + CHW);

    for (int phi = plo; phi < phi_end; phi++) {
        float c = d_COS[phi], s = d_SIN[phi];
        float lim = 2.f * (fabsf(c) + fabsf(s)) + 1e-2f;
        float r0 = -X*s + Y*c;
        float t0 =  X*c + Y*s;
        int mlo = max(0,      (int)ceilf ((r0 + 200.f - lim) * inv_dr));
        int mhi = min(NRAD-1, (int)floorf((r0 + 200.f + lim) * inv_dr));
        int nlo = max(0,      (int)ceilf ((t0 + 350.f - lim) * 0.5f));
        int nhi = min(NT-1,   (int)floorf((t0 + 350.f + lim) * 0.5f));
        int ncnt = nhi - nlo;
        if (ncnt < 0 || mhi < mlo) continue;

        float hc = 0.5f * c, hs = 0.5f * s;
        float tn0 = -350.f + 2.f * (float)nlo;

        for (int m = mlo; m <= mhi; m++) {
            float rm = d_RV[m];
            float Kx = __fmaf_rn(rm, -hs, cx);
            float Ky = __fmaf_rn(rm,  hc, cy);
            float W = 0.f;
            if (interior) {
                float tn = tn0;
                for (int n = 0; n <= ncnt; n++, tn += 2.f) {
                    float dx = __fmaf_rn(tn, hc, Kx);
                    float dy = __fmaf_rn(tn, hs, Ky);
                    float wx = fmaxf(1.f - fabsf(dx), 0.f);
                    float wy = fmaxf(1.f - fabsf(dy), 0.f);
                    W = __fmaf_rn(wx, wy, W);
                }
            } else {
                float tn = tn0;
                for (int n = 0; n <= ncnt; n++, tn += 2.f) {
                    float dx = __fmaf_rn(tn, hc, Kx);
                    float dy = __fmaf_rn(tn, hs, Ky);
                    if (dx < vxl || dx > vxh || dy < vyl || dy > vyh) continue;
                    float wx = fmaxf(1.f - fabsf(dx), 0.f);
                    float wy = fmaxf(1.f - fabsf(dy), 0.f);
                    W = __fmaf_rn(wx, wy, W);
                }
            }
            if (W != 0.f) {
                const ulonglong2* zp = (const ulonglong2*)(zr + (phi*NRAD + m)*N0);
                ulonglong2 p0 = zp[0], p1 = zp[1], p2 = zp[2], p3 = zp[3];
                unsigned long long Wp = f2_pack(W, W);
                f2_fma(accp[0], Wp, p0.x);
                f2_fma(accp[1], Wp, p0.y);
                f2_fma(accp[2], Wp, p1.x);
                f2_fma(accp[3], Wp, p1.y);
                f2_fma(accp[4], Wp, p2.x);
                f2_fma(accp[5], Wp, p2.y);
                f2_fma(accp[6], Wp, p3.x);
                f2_fma(accp[7], Wp, p3.y);
            }
        }
    }
    float* dst = bp + ch * NVOX;
    #pragma unroll
    for (int k = 0; k < 8; k++) {
        float2 u2 = f2_unpack(accp[k]);
        dst[(2*k  )*NPIX + pix] = u2.x * 2.f;   // * STEP
        dst[(2*k+1)*NPIX + pix] = u2.y * 2.f;
    }
}

// ---------------- adjoint gauss: fused combine + j-smooth + z-smooth --------
__global__ void k_smooth_jz(const float* __restrict__ bp, float* __restrict__ out)
{
    __shared__ float ta[N0][N2 + 1];
    __shared__ float tj[N0][N2 + 1];
    int i = blockIdx.x;
    // phase 0: combine NCH backprojection partials
    for (int t = threadIdx.x; t < N0*N2; t += blockDim.x) {
        int j = t % N2;
        int z = t / N2;
        const float* base = bp + z*NPIX + i*N2 + j;
        float s = 0.f;
        #pragma unroll
        for (int ch = 0; ch < NCH; ch++)
            s += base[ch*NVOX];
        ta[z][j] = s;
    }
    __syncthreads();
    // phase 1: j-smooth (ta -> tj)
    for (int t = threadIdx.x; t < N0*N2; t += blockDim.x) {
        int j = t % N2;
        int z = t / N2;
        float s = 0.f;
        if (j >= GR && j < N2-GR) {
            #pragma unroll
            for (int d = -GR; d <= GR; d++)
                s += d_GW[d+GR] * ta[z][j+d];
        } else {
            #pragma unroll
            for (int d = -GR; d <= GR; d++)
                s += d_GW[d+GR] * ta[z][refl(j+d, N2)];
        }
        tj[z][j] = s;
    }
    __syncthreads();
    // phase 2: z-smooth -> global
    for (int t = threadIdx.x; t < N0*N2; t += blockDim.x) {
        int j = t % N2;
        int z = t / N2;
        float s = 0.f;
        #pragma unroll
        for (int d = -GR; d <= GR; d++) {
            int m = z + d;
            if (m < 0)   m = -1 - m;
            if (m >= N0) m = 2*N0 - 1 - m;
            s += d_GW[d+GR] * tj[m][j];
        }
        out[z*NPIX + i*N2 + j] = s;
    }
}

// ---------------- adjoint i-smooth + MLEM update -----------------------------
__global__ void k_smooth_i_final(const float* __restrict__ gin,
                                 const float* __restrict__ x,
                                 const float* __restrict__ sens,
                                 float* __restrict__ out)
{
    int t = blockIdx.x * blockDim.x + threadIdx.x;
    if (t >= NVOX) return;
    int j = t % N2;
    int i = (t / N2) % N1;
    int z = t / NPIX;
    const float* base = gin + z*NPIX + j;
    float s = 0.f;
    if (i >= GR && i < N1-GR) {
        #pragma unroll
        for (int d = -GR; d <= GR; d++)
            s += d_GW[d+GR] * base[(i+d) * N2];
    } else {
        #pragma unroll
        for (int d = -GR; d <= GR; d++)
            s += d_GW[d+GR] * base[refl(i+d, N1) * N2];
    }
    out[t] = x[t] * s / sens[t];
}

// ---------------- launch ----------------------------------------------------
extern "C" void kernel_launch(void* const* d_in, const int* in_sizes, int n_in,
                              void* d_out, int out_size)
{
    const float* x      = (const float*)d_in[0];
    const float* data   = (const float*)d_in[1];
    const float* contam = (const float*)d_in[2];
    const float* mult   = (const float*)d_in[3];
    const float* sens   = (const float*)d_in[4];
    float* out = (float*)d_out;

    float *buf1, *st2, *zr, *bp;
    cudaGetSymbolAddress((void**)&buf1, d_buf1);
    cudaGetSymbolAddress((void**)&st2,  d_st2);
    cudaGetSymbolAddress((void**)&zr,   d_zr);
    cudaGetSymbolAddress((void**)&bp,   d_bp);

    k_init<<<1, 256>>>();

    // forward: fused gauss3 + paired transposed image
    k_gauss3t2<<<N1, 512>>>(x, st2);

    // project + exp + ratio (fused, 8 lanes/ray, checkless hot loop)
    k_project<<<(NSLOT*8 + 255)/256, 256>>>(st2, data, contam, mult, zr);

    // adjoint: backproject (tiled warps + occupancy bound), smooths, MLEM
    k_backproject<<<(NCH*NPIX + 255)/256, 256>>>(zr, bp);
    k_smooth_jz<<<N1, 512>>>(bp, buf1);
    k_smooth_i_final<<<(NVOX + 255)/256, 256>>>(buf1, x, sens, out);
}

// round 13
// speedup vs baseline: 1.1260x; 1.0383x over previous
#include <cuda_runtime.h>

#define N0 16
#define N1 200
#define N2 200
#define NPIX (N1*N2)          // 40000
#define NVOX (N0*NPIX)        // 640000
#define NPHI 190
#define NRAD 223
#define NT 351
#define GR 4                  // gaussian radius
#define NSLOT (NPHI*NRAD)     // 42370
#define NCH 16                // phi chunks for backprojection
#define CHW 12                // ceil(190/16)

// ---------------- scratch (device globals; no allocation allowed) ----------
__device__ __align__(16) float d_GW[2*GR+1];
__device__ float d_COS[NPHI];
__device__ float d_SIN[NPHI];
__device__ float d_RV[NRAD];
__device__ __align__(16) float d_buf1[NVOX];
__device__ __align__(16) float d_st2[2*NVOX + 2*N0*N2];  // paired img + pad i-row
__device__ __align__(16) float d_zr[NSLOT*N0];           // mult*data/exp, [sidx][z]
__device__ __align__(16) float d_bp[NCH*NVOX];           // backprojection partials

// ---------------- packed f32x2 helpers (Blackwell) --------------------------
__device__ __forceinline__ unsigned long long f2_pack(float a, float b)
{
    unsigned long long r;
    asm("mov.b64 %0, {%1,%2};" : "=l"(r) : "f"(a), "f"(b));
    return r;
}
__device__ __forceinline__ void f2_fma(unsigned long long& d,
                                       unsigned long long a, unsigned long long b)
{
    asm("fma.rn.f32x2 %0, %1, %2, %0;" : "+l"(d) : "l"(a), "l"(b));
}
__device__ __forceinline__ unsigned long long f2_add(unsigned long long a,
                                                     unsigned long long b)
{
    unsigned long long r;
    asm("add.rn.f32x2 %0, %1, %2;" : "=l"(r) : "l"(a), "l"(b));
    return r;
}
__device__ __forceinline__ float2 f2_unpack(unsigned long long v)
{
    float2 r;
    asm("mov.b64 {%0,%1}, %2;" : "=f"(r.x), "=f"(r.y) : "l"(v));
    return r;
}

// ---------------- constant tables (match numpy float64 -> float32) ---------
__global__ void k_init()
{
    int t = blockIdx.x * blockDim.x + threadIdx.x;
    if (t == 0) {
        const double sigma = 4.5 / (2.35 * 2.0);
        double g[2*GR+1];
        double sum = 0.0;
        for (int k = 0; k <= 2*GR; k++) {
            double d = (double)(k - GR) / sigma;
            g[k] = exp(-0.5 * d * d);
            sum += g[k];
        }
        for (int k = 0; k <= 2*GR; k++) d_GW[k] = (float)(g[k] / sum);
    }
    const double PI = 3.14159265358979323846;
    for (int i = t; i < NPHI; i += blockDim.x * gridDim.x) {
        float phi = (float)((double)i * (PI / 190.0));   // linspace f64 -> f32
        d_COS[i] = (float)cos((double)phi);
        d_SIN[i] = (float)sin((double)phi);
    }
    for (int i = t; i < NRAD; i += blockDim.x * gridDim.x) {
        d_RV[i] = (float)(-200.0 + (double)i * (400.0 / 222.0));
    }
}

__device__ __forceinline__ int refl(int m, int n)
{
    if (m < 0)  m = -1 - m;
    if (m >= n) m = 2*n - 1 - m;
    return m;
}

// ---------------- fused forward gauss3 + paired z-transpose -----------------
__global__ void k_gauss3t2(const float* __restrict__ in, float* __restrict__ out2)
{
    __shared__ float ta[N0][N2 + 1];
    __shared__ float tb[N0][N2 + 1];
    int i = blockIdx.x;
    int ridx[2*GR+1];
    #pragma unroll
    for (int d = -GR; d <= GR; d++) ridx[d+GR] = refl(i + d, N1);
    // phase 1: i-smooth
    for (int t = threadIdx.x; t < N0*N2; t += blockDim.x) {
        int j = t % N2;
        int z = t / N2;
        const float* base = in + z*NPIX + j;
        float s = 0.f;
        #pragma unroll
        for (int d = 0; d < 2*GR+1; d++)
            s += d_GW[d] * base[ridx[d]*N2];
        ta[z][j] = s;
    }
    __syncthreads();
    // phase 2: j-smooth (ta -> tb)
    for (int t = threadIdx.x; t < N0*N2; t += blockDim.x) {
        int j = t % N2;
        int z = t / N2;
        float s = 0.f;
        if (j >= GR && j < N2-GR) {
            #pragma unroll
            for (int d = -GR; d <= GR; d++)
                s += d_GW[d+GR] * ta[z][j+d];
        } else {
            #pragma unroll
            for (int d = -GR; d <= GR; d++)
                s += d_GW[d+GR] * ta[z][refl(j+d, N2)];
        }
        tb[z][j] = s;
    }
    __syncthreads();
    // phase 3: z-smooth (tb -> ta)
    for (int t = threadIdx.x; t < N0*N2; t += blockDim.x) {
        int j = t % N2;
        int z = t / N2;
        float s = 0.f;
        #pragma unroll
        for (int d = -GR; d <= GR; d++) {
            int m = z + d;
            if (m < 0)   m = -1 - m;
            if (m >= N0) m = 2*N0 - 1 - m;
            s += d_GW[d+GR] * tb[m][j];
        }
        ta[z][j] = s;
    }
    __syncthreads();
    // phase 4: paired-z writes
    for (int t = threadIdx.x; t < N0*N2; t += blockDim.x) {
        int z = t & (N0-1);
        int j = t >> 4;
        int j1 = min(j + 1, N2 - 1);
        float v0 = ta[z][j];
        float v1 = ta[z][j1];
        unsigned base = ((unsigned)(i*N2 + j)) << 5;
        out2[base + z]      = v0;
        out2[base + N0 + z] = v1;
        if (i == N1-1) {   // pad row i = N1 duplicates i = N1-1
            unsigned pbase = ((unsigned)(N1*N2 + j)) << 5;
            out2[pbase + z]      = v0;
            out2[pbase + N0 + z] = v1;
        }
    }
}

// ---------------- forward projection + ratio (fused) ------------------------
__global__ void k_project(const float* __restrict__ st2,
                          const float* __restrict__ data,
                          const float* __restrict__ contam,
                          const float* __restrict__ mult,
                          float* __restrict__ zr)
{
    int t = blockIdx.x * blockDim.x + threadIdx.x;
    int lane8 = t & 7;
    int ray   = t >> 3;
    bool live = (ray < NSLOT);
    if (!live) ray = NSLOT - 1;           // clamp: keep all 32 lanes for shfl
    int phi = ray / NRAD;
    int rad = ray - phi * NRAD;
    int zq  = lane8 & 3;
    bool isj1 = lane8 >= 4;
    float wjb = isj1 ? 0.f : 1.f;         // wj = fma(fj, wjs, wjb)
    float wjs = isj1 ? 1.f : -1.f;

    float c = d_COS[phi], s = d_SIN[phi];
    float r = d_RV[rad];
    float rns = r * (-s);
    float rc  = r * c;

    float A = 0.5f * (rns + 199.f) - 175.f * c;
    float B = 0.5f * (rc  + 199.f) - 175.f * s;

    const float EPS = 1e-6f;
    float lo = 0.f, hi = 350.f;
    bool empty = false;
    if (fabsf(c) > EPS) {
        float n0 = (0.f   - A) / c;
        float n1 = (199.f - A) / c;
        lo = fmaxf(lo, fminf(n0, n1)); hi = fminf(hi, fmaxf(n0, n1));
    } else if (A < 0.f || A > 199.f) empty = true;
    if (fabsf(s) > EPS) {
        float n0 = (0.f   - B) / s;
        float n1 = (199.f - B) / s;
        lo = fmaxf(lo, fminf(n0, n1)); hi = fminf(hi, fmaxf(n0, n1));
    } else if (B < 0.f || B > 199.f) empty = true;

    unsigned long long acc01 = 0ull, acc23 = 0ull;
    if (!empty && hi >= lo) {
        int nlo = max(0,    (int)floorf(lo) - 1);
        int nhi = min(NT-1, (int)ceilf (hi) + 1);
        float hc = 0.5f * c, hs = 0.5f * s;
        float Kx = 0.5f * (rns + 199.f);
        float Ky = 0.5f * (rc  + 199.f);

        // trim to the exact valid contiguous interval (same fp formula)
        while (nlo <= nhi) {
            float tn = -350.f + 2.f * (float)nlo;
            float ix = __fmaf_rn(tn, hc, Kx);
            float iy = __fmaf_rn(tn, hs, Ky);
            if (ix >= 0.f && ix <= 199.f && iy >= 0.f && iy <= 199.f) break;
            nlo++;
        }
        while (nhi >= nlo) {
            float tn = -350.f + 2.f * (float)nhi;
            float ix = __fmaf_rn(tn, hc, Kx);
            float iy = __fmaf_rn(tn, hs, Ky);
            if (ix >= 0.f && ix <= 199.f && iy >= 0.f && iy <= 199.f) break;
            nhi--;
        }

        float tn = -350.f + 2.f * (float)nlo;
        #pragma unroll 4
        for (int n = nlo; n <= nhi; n++, tn += 2.f) {
            float ix = __fmaf_rn(tn, hc, Kx);
            float iy = __fmaf_rn(tn, hs, Ky);
            int i0 = (int)ix;
            int j0 = (int)iy;
            float fi = ix - (float)i0;
            float fj = iy - (float)j0;
            float wj = __fmaf_rn(fj, wjs, wjb);
            unsigned base = ((unsigned)(i0*N2 + j0)) << 5;
            const unsigned iofs = (unsigned)(N2*2*N0);            // pad row
            ulonglong2 q0 = *((const ulonglong2*)(st2 + base) + lane8);
            ulonglong2 q1 = *((const ulonglong2*)(st2 + base + iofs) + lane8);
            float w0 = wj * (1.f - fi);
            float w1 = wj * fi;
            unsigned long long w0p = f2_pack(w0, w0);
            unsigned long long w1p = f2_pack(w1, w1);
            f2_fma(acc01, w0p, q0.x);
            f2_fma(acc01, w1p, q1.x);
            f2_fma(acc23, w0p, q0.y);
            f2_fma(acc23, w1p, q1.y);
        }
    }

    acc01 = f2_add(acc01, __shfl_down_sync(0xffffffffu, acc01, 4));
    acc23 = f2_add(acc23, __shfl_down_sync(0xffffffffu, acc23, 4));

    if (live && !isj1) {
        int sidx = ray;
        float2 u01 = f2_unpack(acc01);
        float2 u23 = f2_unpack(acc23);
        float pr[4] = { u01.x*2.f, u01.y*2.f, u23.x*2.f, u23.y*2.f };
        float4 o;
        float* ov = (float*)&o;
        #pragma unroll
        for (int k = 0; k < 4; k++) {
            int gi = (zq*4 + k) * NSLOT + sidx;
            float mm = mult[gi];
            float e  = __fmaf_rn(mm, pr[k], contam[gi]);
            ov[k] = mm * data[gi] / e;
        }
        ((float4*)zr)[sidx*4 + zq] = o;
    }
}

// ---------------- backprojection (tiled-warp gather) ------------------------
// one thread = (pixel, phi-chunk); warp covers an 8j x 4i pixel tile.
// NCH=16: 2500 blocks -> finer tail quantum / better late-wave balance.
__global__ void __launch_bounds__(256, 5)
k_backproject(const float* __restrict__ zr, float* __restrict__ bp)
{
    int tid = blockIdx.x * blockDim.x + threadIdx.x;
    if (tid >= NCH * NPIX) return;
    int ch = tid / NPIX;
    int u  = tid % NPIX;                  // NPIX % 32 == 0: warps stay in-chunk
    int lane = u & 31;
    int wu   = u >> 5;                    // 0..1249
    int ti = wu / (N2/8);                 // 0..49  (i tile)
    int tj = wu % (N2/8);                 // 0..24  (j tile)
    int i = ti*4 + (lane >> 3);
    int j = tj*8 + (lane & 7);
    int pix = i * N2 + j;

    float X = -199.f + 2.f * (float)i;
    float Y = -199.f + 2.f * (float)j;

    unsigned long long accp[8];
    #pragma unroll
    for (int k = 0; k < 8; k++) accp[k] = 0ull;

    const float inv_dr = (float)(222.0 / 400.0);
    float cx = 99.5f - (float)i;
    float cy = 99.5f - (float)j;
    float vxl = -(float)i,  vxh = 199.f - (float)i;
    float vyl = -(float)j,  vyh = 199.f - (float)j;
    bool interior = (i >= 1 && i <= N1-2 && j >= 1 && j <= N2-2);

    int plo = ch * CHW;
    int phi_end = min(NPHI, plo + CHW);

    for (int phi = plo; phi < phi_end; phi++) {
        float c = d_COS[phi], s = d_SIN[phi];
        float lim = 2.f * (fabsf(c) + fabsf(s)) + 1e-2f;
        float r0 = -X*s + Y*c;
        float t0 =  X*c + Y*s;
        int mlo = max(0,      (int)ceilf ((r0 + 200.f - lim) * inv_dr));
        int mhi = min(NRAD-1, (int)floorf((r0 + 200.f + lim) * inv_dr));
        int nlo = max(0,      (int)ceilf ((t0 + 350.f - lim) * 0.5f));
        int nhi = min(NT-1,   (int)floorf((t0 + 350.f + lim) * 0.5f));
        int ncnt = nhi - nlo;
        if (ncnt < 0 || mhi < mlo) continue;

        float hc = 0.5f * c, hs = 0.5f * s;
        float tn0 = -350.f + 2.f * (float)nlo;

        for (int m = mlo; m <= mhi; m++) {
            float rm = d_RV[m];
            float Kx = __fmaf_rn(rm, -hs, cx);
            float Ky = __fmaf_rn(rm,  hc, cy);
            float W = 0.f;
            if (interior) {
                float tn = tn0;
                for (int n = 0; n <= ncnt; n++, tn += 2.f) {
                    float dx = __fmaf_rn(tn, hc, Kx);
                    float dy = __fmaf_rn(tn, hs, Ky);
                    float wx = fmaxf(1.f - fabsf(dx), 0.f);
                    float wy = fmaxf(1.f - fabsf(dy), 0.f);
                    W = __fmaf_rn(wx, wy, W);
                }
            } else {
                float tn = tn0;
                for (int n = 0; n <= ncnt; n++, tn += 2.f) {
                    float dx = __fmaf_rn(tn, hc, Kx);
                    float dy = __fmaf_rn(tn, hs, Ky);
                    if (dx < vxl || dx > vxh || dy < vyl || dy > vyh) continue;
                    float wx = fmaxf(1.f - fabsf(dx), 0.f);
                    float wy = fmaxf(1.f - fabsf(dy), 0.f);
                    W = __fmaf_rn(wx, wy, W);
                }
            }
            if (W != 0.f) {
                const ulonglong2* zp = (const ulonglong2*)(zr + (phi*NRAD + m)*N0);
                ulonglong2 p0 = zp[0], p1 = zp[1], p2 = zp[2], p3 = zp[3];
                unsigned long long Wp = f2_pack(W, W);
                f2_fma(accp[0], Wp, p0.x);
                f2_fma(accp[1], Wp, p0.y);
                f2_fma(accp[2], Wp, p1.x);
                f2_fma(accp[3], Wp, p1.y);
                f2_fma(accp[4], Wp, p2.x);
                f2_fma(accp[5], Wp, p2.y);
                f2_fma(accp[6], Wp, p3.x);
                f2_fma(accp[7], Wp, p3.y);
            }
        }
    }
    float* dst = bp + ch * NVOX;
    #pragma unroll
    for (int k = 0; k < 8; k++) {
        float2 u2 = f2_unpack(accp[k]);
        dst[(2*k  )*NPIX + pix] = u2.x * 2.f;   // * STEP
        dst[(2*k+1)*NPIX + pix] = u2.y * 2.f;
    }
}

// ---------------- adjoint gauss: fused combine + j-smooth + z-smooth --------
__global__ void k_smooth_jz(const float* __restrict__ bp, float* __restrict__ out)
{
    __shared__ float ta[N0][N2 + 1];
    __shared__ float tj[N0][N2 + 1];
    int i = blockIdx.x;
    // phase 0: combine NCH backprojection partials
    for (int t = threadIdx.x; t < N0*N2; t += blockDim.x) {
        int j = t % N2;
        int z = t / N2;
        const float* base = bp + z*NPIX + i*N2 + j;
        float s = 0.f;
        #pragma unroll
        for (int ch = 0; ch < NCH; ch++)
            s += base[ch*NVOX];
        ta[z][j] = s;
    }
    __syncthreads();
    // phase 1: j-smooth (ta -> tj)
    for (int t = threadIdx.x; t < N0*N2; t += blockDim.x) {
        int j = t % N2;
        int z = t / N2;
        float s = 0.f;
        if (j >= GR && j < N2-GR) {
            #pragma unroll
            for (int d = -GR; d <= GR; d++)
                s += d_GW[d+GR] * ta[z][j+d];
        } else {
            #pragma unroll
            for (int d = -GR; d <= GR; d++)
                s += d_GW[d+GR] * ta[z][refl(j+d, N2)];
        }
        tj[z][j] = s;
    }
    __syncthreads();
    // phase 2: z-smooth -> global
    for (int t = threadIdx.x; t < N0*N2; t += blockDim.x) {
        int j = t % N2;
        int z = t / N2;
        float s = 0.f;
        #pragma unroll
        for (int d = -GR; d <= GR; d++) {
            int m = z + d;
            if (m < 0)   m = -1 - m;
            if (m >= N0) m = 2*N0 - 1 - m;
            s += d_GW[d+GR] * tj[m][j];
        }
        out[z*NPIX + i*N2 + j] = s;
    }
}

// ---------------- adjoint i-smooth + MLEM update -----------------------------
__global__ void k_smooth_i_final(const float* __restrict__ gin,
                                 const float* __restrict__ x,
                                 const float* __restrict__ sens,
                                 float* __restrict__ out)
{
    int t = blockIdx.x * blockDim.x + threadIdx.x;
    if (t >= NVOX) return;
    int j = t % N2;
    int i = (t / N2) % N1;
    int z = t / NPIX;
    const float* base = gin + z*NPIX + j;
    float s = 0.f;
    if (i >= GR && i < N1-GR) {
        #pragma unroll
        for (int d = -GR; d <= GR; d++)
            s += d_GW[d+GR] * base[(i+d) * N2];
    } else {
        #pragma unroll
        for (int d = -GR; d <= GR; d++)
            s += d_GW[d+GR] * base[refl(i+d, N1) * N2];
    }
    out[t] = x[t] * s / sens[t];
}

// ---------------- launch ----------------------------------------------------
extern "C" void kernel_launch(void* const* d_in, const int* in_sizes, int n_in,
                              void* d_out, int out_size)
{
    const float* x      = (const float*)d_in[0];
    const float* data   = (const float*)d_in[1];
    const float* contam = (const float*)d_in[2];
    const float* mult   = (const float*)d_in[3];
    const float* sens   = (const float*)d_in[4];
    float* out = (float*)d_out;

    float *buf1, *st2, *zr, *bp;
    cudaGetSymbolAddress((void**)&buf1, d_buf1);
    cudaGetSymbolAddress((void**)&st2,  d_st2);
    cudaGetSymbolAddress((void**)&zr,   d_zr);
    cudaGetSymbolAddress((void**)&bp,   d_bp);

    k_init<<<1, 256>>>();

    // forward: fused gauss3 + paired transposed image
    k_gauss3t2<<<N1, 512>>>(x, st2);

    // project + exp + ratio (fused, 8 lanes/ray, checkless unrolled hot loop)
    k_project<<<(NSLOT*8 + 255)/256, 256>>>(st2, data, contam, mult, zr);

    // adjoint: backproject (tiled warps, NCH=16), smooths, MLEM
    k_backproject<<<(NCH*NPIX + 255)/256, 256>>>(zr, bp);
    k_smooth_jz<<<N1, 512>>>(bp, buf1);
    k_smooth_i_final<<<(NVOX + 255)/256, 256>>>(buf1, x, sens, out);
}

// round 15
// speedup vs baseline: 1.1406x; 1.0130x over previous
#include <cuda_runtime.h>

#define N0 16
#define N1 200
#define N2 200
#define NPIX (N1*N2)          // 40000
#define NVOX (N0*NPIX)        // 640000
#define NPHI 190
#define NRAD 223
#define NT 351
#define GR 4                  // gaussian radius
#define NSLOT (NPHI*NRAD)     // 42370
#define NCH 16                // phi chunks for backprojection
#define CHW 12                // ceil(190/16)

// ---------------- scratch (device globals; no allocation allowed) ----------
__device__ __align__(16) float d_GW[2*GR+1];
__device__ float d_COS[NPHI];
__device__ float d_SIN[NPHI];
__device__ float d_RV[NRAD];
__device__ __align__(16) float d_buf1[NVOX];
__device__ __align__(16) float d_st2[2*NVOX + 2*N0*N2];  // paired img + pad i-row
__device__ __align__(16) float d_zr[NSLOT*N0];           // mult*data/exp, [sidx][z]
__device__ __align__(16) float d_bp[NCH*NVOX];           // backprojection partials

// ---------------- packed f32x2 helpers (Blackwell) --------------------------
__device__ __forceinline__ unsigned long long f2_pack(float a, float b)
{
    unsigned long long r;
    asm("mov.b64 %0, {%1,%2};" : "=l"(r) : "f"(a), "f"(b));
    return r;
}
__device__ __forceinline__ void f2_fma(unsigned long long& d,
                                       unsigned long long a, unsigned long long b)
{
    asm("fma.rn.f32x2 %0, %1, %2, %0;" : "+l"(d) : "l"(a), "l"(b));
}
__device__ __forceinline__ unsigned long long f2_add(unsigned long long a,
                                                     unsigned long long b)
{
    unsigned long long r;
    asm("add.rn.f32x2 %0, %1, %2;" : "=l"(r) : "l"(a), "l"(b));
    return r;
}
__device__ __forceinline__ float2 f2_unpack(unsigned long long v)
{
    float2 r;
    asm("mov.b64 {%0,%1}, %2;" : "=f"(r.x), "=f"(r.y) : "l"(v));
    return r;
}

__device__ __forceinline__ int refl(int m, int n)
{
    if (m < 0)  m = -1 - m;
    if (m >= n) m = 2*n - 1 - m;
    return m;
}

// ---------------- fused init + forward gauss3 + paired z-transpose ----------
// block 0 additionally writes the global constant tables (used by later
// kernels); every block computes the 9 gaussian weights locally.
__global__ void k_gauss3t2(const float* __restrict__ in, float* __restrict__ out2)
{
    __shared__ float ta[N0][N2 + 1];
    __shared__ float tb[N0][N2 + 1];
    __shared__ float sGW[2*GR+1];
    int i = blockIdx.x;

    if (threadIdx.x == 0) {
        const double sigma = 4.5 / (2.35 * 2.0);
        double g[2*GR+1];
        double sum = 0.0;
        for (int k = 0; k <= 2*GR; k++) {
            double dd = (double)(k - GR) / sigma;
            g[k] = exp(-0.5 * dd * dd);
            sum += g[k];
        }
        for (int k = 0; k <= 2*GR; k++) {
            float w = (float)(g[k] / sum);
            sGW[k] = w;
            if (i == 0) d_GW[k] = w;
        }
    }
    if (i == 0) {
        const double PI = 3.14159265358979323846;
        for (int t = threadIdx.x; t < NPHI; t += blockDim.x) {
            float phi = (float)((double)t * (PI / 190.0));
            d_COS[t] = (float)cos((double)phi);
            d_SIN[t] = (float)sin((double)phi);
        }
        for (int t = threadIdx.x; t < NRAD; t += blockDim.x)
            d_RV[t] = (float)(-200.0 + (double)t * (400.0 / 222.0));
    }
    __syncthreads();

    int ridx[2*GR+1];
    #pragma unroll
    for (int d = -GR; d <= GR; d++) ridx[d+GR] = refl(i + d, N1);
    // phase 1: i-smooth
    for (int t = threadIdx.x; t < N0*N2; t += blockDim.x) {
        int j = t % N2;
        int z = t / N2;
        const float* base = in + z*NPIX + j;
        float s = 0.f;
        #pragma unroll
        for (int d = 0; d < 2*GR+1; d++)
            s += sGW[d] * base[ridx[d]*N2];
        ta[z][j] = s;
    }
    __syncthreads();
    // phase 2: j-smooth (ta -> tb)
    for (int t = threadIdx.x; t < N0*N2; t += blockDim.x) {
        int j = t % N2;
        int z = t / N2;
        float s = 0.f;
        if (j >= GR && j < N2-GR) {
            #pragma unroll
            for (int d = -GR; d <= GR; d++)
                s += sGW[d+GR] * ta[z][j+d];
        } else {
            #pragma unroll
            for (int d = -GR; d <= GR; d++)
                s += sGW[d+GR] * ta[z][refl(j+d, N2)];
        }
        tb[z][j] = s;
    }
    __syncthreads();
    // phase 3: z-smooth (tb -> ta)
    for (int t = threadIdx.x; t < N0*N2; t += blockDim.x) {
        int j = t % N2;
        int z = t / N2;
        float s = 0.f;
        #pragma unroll
        for (int d = -GR; d <= GR; d++) {
            int m = z + d;
            if (m < 0)   m = -1 - m;
            if (m >= N0) m = 2*N0 - 1 - m;
            s += sGW[d+GR] * tb[m][j];
        }
        ta[z][j] = s;
    }
    __syncthreads();
    // phase 4: paired-z writes
    for (int t = threadIdx.x; t < N0*N2; t += blockDim.x) {
        int z = t & (N0-1);
        int j = t >> 4;
        int j1 = min(j + 1, N2 - 1);
        float v0 = ta[z][j];
        float v1 = ta[z][j1];
        unsigned base = ((unsigned)(i*N2 + j)) << 5;
        out2[base + z]      = v0;
        out2[base + N0 + z] = v1;
        if (i == N1-1) {   // pad row i = N1 duplicates i = N1-1
            unsigned pbase = ((unsigned)(N1*N2 + j)) << 5;
            out2[pbase + z]      = v0;
            out2[pbase + N0 + z] = v1;
        }
    }
}

// ---------------- forward projection + ratio (fused) ------------------------
__global__ void k_project(const float* __restrict__ st2,
                          const float* __restrict__ data,
                          const float* __restrict__ contam,
                          const float* __restrict__ mult,
                          float* __restrict__ zr)
{
    int t = blockIdx.x * blockDim.x + threadIdx.x;
    int lane8 = t & 7;
    int ray   = t >> 3;
    bool live = (ray < NSLOT);
    if (!live) ray = NSLOT - 1;           // clamp: keep all 32 lanes for shfl
    int phi = ray / NRAD;
    int rad = ray - phi * NRAD;
    int zq  = lane8 & 3;
    bool isj1 = lane8 >= 4;
    float wjb = isj1 ? 0.f : 1.f;         // wj = fma(fj, wjs, wjb)
    float wjs = isj1 ? 1.f : -1.f;

    float c = d_COS[phi], s = d_SIN[phi];
    float r = d_RV[rad];
    float rns = r * (-s);
    float rc  = r * c;

    float A = 0.5f * (rns + 199.f) - 175.f * c;
    float B = 0.5f * (rc  + 199.f) - 175.f * s;

    const float EPS = 1e-6f;
    float lo = 0.f, hi = 350.f;
    bool empty = false;
    if (fabsf(c) > EPS) {
        float n0 = (0.f   - A) / c;
        float n1 = (199.f - A) / c;
        lo = fmaxf(lo, fminf(n0, n1)); hi = fminf(hi, fmaxf(n0, n1));
    } else if (A < 0.f || A > 199.f) empty = true;
    if (fabsf(s) > EPS) {
        float n0 = (0.f   - B) / s;
        float n1 = (199.f - B) / s;
        lo = fmaxf(lo, fminf(n0, n1)); hi = fminf(hi, fmaxf(n0, n1));
    } else if (B < 0.f || B > 199.f) empty = true;

    unsigned long long acc01 = 0ull, acc23 = 0ull;
    if (!empty && hi >= lo) {
        int nlo = max(0,    (int)floorf(lo) - 1);
        int nhi = min(NT-1, (int)ceilf (hi) + 1);
        float hc = 0.5f * c, hs = 0.5f * s;
        float Kx = 0.5f * (rns + 199.f);
        float Ky = 0.5f * (rc  + 199.f);

        // trim to the exact valid contiguous interval (same fp formula)
        while (nlo <= nhi) {
            float tn = -350.f + 2.f * (float)nlo;
            float ix = __fmaf_rn(tn, hc, Kx);
            float iy = __fmaf_rn(tn, hs, Ky);
            if (ix >= 0.f && ix <= 199.f && iy >= 0.f && iy <= 199.f) break;
            nlo++;
        }
        while (nhi >= nlo) {
            float tn = -350.f + 2.f * (float)nhi;
            float ix = __fmaf_rn(tn, hc, Kx);
            float iy = __fmaf_rn(tn, hs, Ky);
            if (ix >= 0.f && ix <= 199.f && iy >= 0.f && iy <= 199.f) break;
            nhi--;
        }

        float tn = -350.f + 2.f * (float)nlo;
        #pragma unroll 4
        for (int n = nlo; n <= nhi; n++, tn += 2.f) {
            float ix = __fmaf_rn(tn, hc, Kx);
            float iy = __fmaf_rn(tn, hs, Ky);
            int i0 = (int)ix;
            int j0 = (int)iy;
            float fi = ix - (float)i0;
            float fj = iy - (float)j0;
            float wj = __fmaf_rn(fj, wjs, wjb);
            unsigned base = ((unsigned)(i0*N2 + j0)) << 5;
            const unsigned iofs = (unsigned)(N2*2*N0);            // pad row
            ulonglong2 q0 = *((const ulonglong2*)(st2 + base) + lane8);
            ulonglong2 q1 = *((const ulonglong2*)(st2 + base + iofs) + lane8);
            float w0 = wj * (1.f - fi);
            float w1 = wj * fi;
            unsigned long long w0p = f2_pack(w0, w0);
            unsigned long long w1p = f2_pack(w1, w1);
            f2_fma(acc01, w0p, q0.x);
            f2_fma(acc01, w1p, q1.x);
            f2_fma(acc23, w0p, q0.y);
            f2_fma(acc23, w1p, q1.y);
        }
    }

    acc01 = f2_add(acc01, __shfl_down_sync(0xffffffffu, acc01, 4));
    acc23 = f2_add(acc23, __shfl_down_sync(0xffffffffu, acc23, 4));

    if (live && !isj1) {
        int sidx = ray;
        float2 u01 = f2_unpack(acc01);
        float2 u23 = f2_unpack(acc23);
        float pr[4] = { u01.x*2.f, u01.y*2.f, u23.x*2.f, u23.y*2.f };
        float4 o;
        float* ov = (float*)&o;
        #pragma unroll
        for (int k = 0; k < 4; k++) {
            int gi = (zq*4 + k) * NSLOT + sidx;
            float mm = mult[gi];
            float e  = __fmaf_rn(mm, pr[k], contam[gi]);
            ov[k] = mm * data[gi] / e;
        }
        ((float4*)zr)[sidx*4 + zq] = o;
    }
}

// ---------------- backprojection (tiled-warp gather, round-13 body) ---------
// one thread = (pixel, phi-chunk); warp covers an 8j x 4i pixel tile.
__global__ void __launch_bounds__(256, 5)
k_backproject(const float* __restrict__ zr, float* __restrict__ bp)
{
    int tid = blockIdx.x * blockDim.x + threadIdx.x;
    if (tid >= NCH * NPIX) return;
    int ch = tid / NPIX;
    int u  = tid % NPIX;                  // NPIX % 32 == 0: warps stay in-chunk
    int lane = u & 31;
    int wu   = u >> 5;                    // 0..1249
    int ti = wu / (N2/8);                 // 0..49  (i tile)
    int tj = wu % (N2/8);                 // 0..24  (j tile)
    int i = ti*4 + (lane >> 3);
    int j = tj*8 + (lane & 7);
    int pix = i * N2 + j;

    float X = -199.f + 2.f * (float)i;
    float Y = -199.f + 2.f * (float)j;

    unsigned long long accp[8];
    #pragma unroll
    for (int k = 0; k < 8; k++) accp[k] = 0ull;

    const float inv_dr = (float)(222.0 / 400.0);
    float cx = 99.5f - (float)i;
    float cy = 99.5f - (float)j;
    float vxl = -(float)i,  vxh = 199.f - (float)i;
    float vyl = -(float)j,  vyh = 199.f - (float)j;
    bool interior = (i >= 1 && i <= N1-2 && j >= 1 && j <= N2-2);

    int plo = ch * CHW;
    int phi_end = min(NPHI, plo + CHW);

    for (int phi = plo; phi < phi_end; phi++) {
        float c = d_COS[phi], s = d_SIN[phi];
        float lim = 2.f * (fabsf(c) + fabsf(s)) + 1e-2f;
        float r0 = -X*s + Y*c;
        float t0 =  X*c + Y*s;
        int mlo = max(0,      (int)ceilf ((r0 + 200.f - lim) * inv_dr));
        int mhi = min(NRAD-1, (int)floorf((r0 + 200.f + lim) * inv_dr));
        int nlo = max(0,      (int)ceilf ((t0 + 350.f - lim) * 0.5f));
        int nhi = min(NT-1,   (int)floorf((t0 + 350.f + lim) * 0.5f));
        int ncnt = nhi - nlo;
        if (ncnt < 0 || mhi < mlo) continue;

        float hc = 0.5f * c, hs = 0.5f * s;
        float tn0 = -350.f + 2.f * (float)nlo;

        for (int m = mlo; m <= mhi; m++) {
            float rm = d_RV[m];
            float Kx = __fmaf_rn(rm, -hs, cx);
            float Ky = __fmaf_rn(rm,  hc, cy);
            float W = 0.f;
            if (interior) {
                float tn = tn0;
                for (int n = 0; n <= ncnt; n++, tn += 2.f) {
                    float dx = __fmaf_rn(tn, hc, Kx);
                    float dy = __fmaf_rn(tn, hs, Ky);
                    float wx = fmaxf(1.f - fabsf(dx), 0.f);
                    float wy = fmaxf(1.f - fabsf(dy), 0.f);
                    W = __fmaf_rn(wx, wy, W);
                }
            } else {
                float tn = tn0;
                for (int n = 0; n <= ncnt; n++, tn += 2.f) {
                    float dx = __fmaf_rn(tn, hc, Kx);
                    float dy = __fmaf_rn(tn, hs, Ky);
                    if (dx < vxl || dx > vxh || dy < vyl || dy > vyh) continue;
                    float wx = fmaxf(1.f - fabsf(dx), 0.f);
                    float wy = fmaxf(1.f - fabsf(dy), 0.f);
                    W = __fmaf_rn(wx, wy, W);
                }
            }
            if (W != 0.f) {
                const ulonglong2* zp = (const ulonglong2*)(zr + (phi*NRAD + m)*N0);
                ulonglong2 p0 = zp[0], p1 = zp[1], p2 = zp[2], p3 = zp[3];
                unsigned long long Wp = f2_pack(W, W);
                f2_fma(accp[0], Wp, p0.x);
                f2_fma(accp[1], Wp, p0.y);
                f2_fma(accp[2], Wp, p1.x);
                f2_fma(accp[3], Wp, p1.y);
                f2_fma(accp[4], Wp, p2.x);
                f2_fma(accp[5], Wp, p2.y);
                f2_fma(accp[6], Wp, p3.x);
                f2_fma(accp[7], Wp, p3.y);
            }
        }
    }
    float* dst = bp + ch * NVOX;
    #pragma unroll
    for (int k = 0; k < 8; k++) {
        float2 u2 = f2_unpack(accp[k]);
        dst[(2*k  )*NPIX + pix] = u2.x * 2.f;   // * STEP
        dst[(2*k+1)*NPIX + pix] = u2.y * 2.f;
    }
}

// ---------------- adjoint gauss: fused combine + j-smooth + z-smooth --------
__global__ void k_smooth_jz(const float* __restrict__ bp, float* __restrict__ out)
{
    __shared__ float ta[N0][N2 + 1];
    __shared__ float tj[N0][N2 + 1];
    int i = blockIdx.x;
    // phase 0: combine NCH backprojection partials
    for (int t = threadIdx.x; t < N0*N2; t += blockDim.x) {
        int j = t % N2;
        int z = t / N2;
        const float* base = bp + z*NPIX + i*N2 + j;
        float s = 0.f;
        #pragma unroll
        for (int ch = 0; ch < NCH; ch++)
            s += base[ch*NVOX];
        ta[z][j] = s;
    }
    __syncthreads();
    // phase 1: j-smooth (ta -> tj)
    for (int t = threadIdx.x; t < N0*N2; t += blockDim.x) {
        int j = t % N2;
        int z = t / N2;
        float s = 0.f;
        if (j >= GR && j < N2-GR) {
            #pragma unroll
            for (int d = -GR; d <= GR; d++)
                s += d_GW[d+GR] * ta[z][j+d];
        } else {
            #pragma unroll
            for (int d = -GR; d <= GR; d++)
                s += d_GW[d+GR] * ta[z][refl(j+d, N2)];
        }
        tj[z][j] = s;
    }
    __syncthreads();
    // phase 2: z-smooth -> global
    for (int t = threadIdx.x; t < N0*N2; t += blockDim.x) {
        int j = t % N2;
        int z = t / N2;
        float s = 0.f;
        #pragma unroll
        for (int d = -GR; d <= GR; d++) {
            int m = z + d;
            if (m < 0)   m = -1 - m;
            if (m >= N0) m = 2*N0 - 1 - m;
            s += d_GW[d+GR] * tj[m][j];
        }
        out[z*NPIX + i*N2 + j] = s;
    }
}

// ---------------- adjoint i-smooth + MLEM update -----------------------------
__global__ void k_smooth_i_final(const float* __restrict__ gin,
                                 const float* __restrict__ x,
                                 const float* __restrict__ sens,
                                 float* __restrict__ out)
{
    int t = blockIdx.x * blockDim.x + threadIdx.x;
    if (t >= NVOX) return;
    int j = t % N2;
    int i = (t / N2) % N1;
    int z = t / NPIX;
    const float* base = gin + z*NPIX + j;
    float s = 0.f;
    if (i >= GR && i < N1-GR) {
        #pragma unroll
        for (int d = -GR; d <= GR; d++)
            s += d_GW[d+GR] * base[(i+d) * N2];
    } else {
        #pragma unroll
        for (int d = -GR; d <= GR; d++)
            s += d_GW[d+GR] * base[refl(i+d, N1) * N2];
    }
    out[t] = x[t] * s / sens[t];
}

// ---------------- launch ----------------------------------------------------
extern "C" void kernel_launch(void* const* d_in, const int* in_sizes, int n_in,
                              void* d_out, int out_size)
{
    const float* x      = (const float*)d_in[0];
    const float* data   = (const float*)d_in[1];
    const float* contam = (const float*)d_in[2];
    const float* mult   = (const float*)d_in[3];
    const float* sens   = (const float*)d_in[4];
    float* out = (float*)d_out;

    float *buf1, *st2, *zr, *bp;
    cudaGetSymbolAddress((void**)&buf1, d_buf1);
    cudaGetSymbolAddress((void**)&st2,  d_st2);
    cudaGetSymbolAddress((void**)&zr,   d_zr);
    cudaGetSymbolAddress((void**)&bp,   d_bp);

    // forward: fused init + gauss3 + paired transposed image
    k_gauss3t2<<<N1, 512>>>(x, st2);

    // project + exp + ratio (fused, 8 lanes/ray, checkless unrolled hot loop)
    k_project<<<(NSLOT*8 + 255)/256, 256>>>(st2, data, contam, mult, zr);

    // adjoint: backproject (tiled warps, NCH=16), smooths, MLEM
    k_backproject<<<(NCH*NPIX + 255)/256, 256>>>(zr, bp);
    k_smooth_jz<<<N1, 512>>>(bp, buf1);
    k_smooth_i_final<<<(NVOX + 255)/256, 256>>>(buf1, x, sens, out);
}

// round 16
// speedup vs baseline: 1.2795x; 1.1218x over previous
#include <cuda_runtime.h>
#include <cuda_fp16.h>

#define N0 16
#define N1 200
#define N2 200
#define NPIX (N1*N2)          // 40000
#define NVOX (N0*NPIX)        // 640000
#define NPHI 190
#define NRAD 223
#define NT 351
#define GR 4                  // gaussian radius
#define NSLOT (NPHI*NRAD)     // 42370
#define NCH 16                // phi chunks for backprojection
#define CHW 12                // ceil(190/16)

// ---------------- scratch (device globals; no allocation allowed) ----------
__device__ __align__(16) float d_GW[2*GR+1];
__device__ float d_COS[NPHI];
__device__ float d_SIN[NPHI];
__device__ float d_RV[NRAD];
__device__ __align__(16) float d_buf1[NVOX];
__device__ __align__(16) float d_st2[2*NVOX + 2*N0*N2];  // paired img + pad i-row
__device__ __align__(32) __half d_zr[NSLOT*N0];          // fp16 mult*data/exp, [sidx][z]
__device__ __align__(16) float d_bp[NCH*NVOX];           // backprojection partials

// ---------------- packed f32x2 helpers (Blackwell) --------------------------
__device__ __forceinline__ unsigned long long f2_pack(float a, float b)
{
    unsigned long long r;
    asm("mov.b64 %0, {%1,%2};" : "=l"(r) : "f"(a), "f"(b));
    return r;
}
__device__ __forceinline__ void f2_fma(unsigned long long& d,
                                       unsigned long long a, unsigned long long b)
{
    asm("fma.rn.f32x2 %0, %1, %2, %0;" : "+l"(d) : "l"(a), "l"(b));
}
__device__ __forceinline__ unsigned long long f2_add(unsigned long long a,
                                                     unsigned long long b)
{
    unsigned long long r;
    asm("add.rn.f32x2 %0, %1, %2;" : "=l"(r) : "l"(a), "l"(b));
    return r;
}
__device__ __forceinline__ float2 f2_unpack(unsigned long long v)
{
    float2 r;
    asm("mov.b64 {%0,%1}, %2;" : "=f"(r.x), "=f"(r.y) : "l"(v));
    return r;
}
// half2 word -> packed f32x2 u64
__device__ __forceinline__ unsigned long long h2_to_f2(unsigned h2)
{
    float2 f = __half22float2(*reinterpret_cast<__half2*>(&h2));
    return f2_pack(f.x, f.y);
}

__device__ __forceinline__ int refl(int m, int n)
{
    if (m < 0)  m = -1 - m;
    if (m >= n) m = 2*n - 1 - m;
    return m;
}

// ---------------- fused init + forward gauss3 + paired z-transpose ----------
__global__ void k_gauss3t2(const float* __restrict__ in, float* __restrict__ out2)
{
    __shared__ float ta[N0][N2 + 1];
    __shared__ float tb[N0][N2 + 1];
    __shared__ float sGW[2*GR+1];
    int i = blockIdx.x;

    if (threadIdx.x == 0) {
        const double sigma = 4.5 / (2.35 * 2.0);
        double g[2*GR+1];
        double sum = 0.0;
        for (int k = 0; k <= 2*GR; k++) {
            double dd = (double)(k - GR) / sigma;
            g[k] = exp(-0.5 * dd * dd);
            sum += g[k];
        }
        for (int k = 0; k <= 2*GR; k++) {
            float w = (float)(g[k] / sum);
            sGW[k] = w;
            if (i == 0) d_GW[k] = w;
        }
    }
    if (i == 0) {
        const double PI = 3.14159265358979323846;
        for (int t = threadIdx.x; t < NPHI; t += blockDim.x) {
            float phi = (float)((double)t * (PI / 190.0));
            d_COS[t] = (float)cos((double)phi);
            d_SIN[t] = (float)sin((double)phi);
        }
        for (int t = threadIdx.x; t < NRAD; t += blockDim.x)
            d_RV[t] = (float)(-200.0 + (double)t * (400.0 / 222.0));
    }
    __syncthreads();

    int ridx[2*GR+1];
    #pragma unroll
    for (int d = -GR; d <= GR; d++) ridx[d+GR] = refl(i + d, N1);
    // phase 1: i-smooth
    for (int t = threadIdx.x; t < N0*N2; t += blockDim.x) {
        int j = t % N2;
        int z = t / N2;
        const float* base = in + z*NPIX + j;
        float s = 0.f;
        #pragma unroll
        for (int d = 0; d < 2*GR+1; d++)
            s += sGW[d] * base[ridx[d]*N2];
        ta[z][j] = s;
    }
    __syncthreads();
    // phase 2: j-smooth (ta -> tb)
    for (int t = threadIdx.x; t < N0*N2; t += blockDim.x) {
        int j = t % N2;
        int z = t / N2;
        float s = 0.f;
        if (j >= GR && j < N2-GR) {
            #pragma unroll
            for (int d = -GR; d <= GR; d++)
                s += sGW[d+GR] * ta[z][j+d];
        } else {
            #pragma unroll
            for (int d = -GR; d <= GR; d++)
                s += sGW[d+GR] * ta[z][refl(j+d, N2)];
        }
        tb[z][j] = s;
    }
    __syncthreads();
    // phase 3: z-smooth (tb -> ta)
    for (int t = threadIdx.x; t < N0*N2; t += blockDim.x) {
        int j = t % N2;
        int z = t / N2;
        float s = 0.f;
        #pragma unroll
        for (int d = -GR; d <= GR; d++) {
            int m = z + d;
            if (m < 0)   m = -1 - m;
            if (m >= N0) m = 2*N0 - 1 - m;
            s += sGW[d+GR] * tb[m][j];
        }
        ta[z][j] = s;
    }
    __syncthreads();
    // phase 4: paired-z writes
    for (int t = threadIdx.x; t < N0*N2; t += blockDim.x) {
        int z = t & (N0-1);
        int j = t >> 4;
        int j1 = min(j + 1, N2 - 1);
        float v0 = ta[z][j];
        float v1 = ta[z][j1];
        unsigned base = ((unsigned)(i*N2 + j)) << 5;
        out2[base + z]      = v0;
        out2[base + N0 + z] = v1;
        if (i == N1-1) {   // pad row i = N1 duplicates i = N1-1
            unsigned pbase = ((unsigned)(N1*N2 + j)) << 5;
            out2[pbase + z]      = v0;
            out2[pbase + N0 + z] = v1;
        }
    }
}

// ---------------- forward projection + ratio (fused, fp16 zr out) -----------
__global__ void k_project(const float* __restrict__ st2,
                          const float* __restrict__ data,
                          const float* __restrict__ contam,
                          const float* __restrict__ mult,
                          __half* __restrict__ zr)
{
    int t = blockIdx.x * blockDim.x + threadIdx.x;
    int lane8 = t & 7;
    int ray   = t >> 3;
    bool live = (ray < NSLOT);
    if (!live) ray = NSLOT - 1;           // clamp: keep all 32 lanes for shfl
    int phi = ray / NRAD;
    int rad = ray - phi * NRAD;
    int zq  = lane8 & 3;
    bool isj1 = lane8 >= 4;
    float wjb = isj1 ? 0.f : 1.f;         // wj = fma(fj, wjs, wjb)
    float wjs = isj1 ? 1.f : -1.f;

    float c = d_COS[phi], s = d_SIN[phi];
    float r = d_RV[rad];
    float rns = r * (-s);
    float rc  = r * c;

    float A = 0.5f * (rns + 199.f) - 175.f * c;
    float B = 0.5f * (rc  + 199.f) - 175.f * s;

    const float EPS = 1e-6f;
    float lo = 0.f, hi = 350.f;
    bool empty = false;
    if (fabsf(c) > EPS) {
        float n0 = (0.f   - A) / c;
        float n1 = (199.f - A) / c;
        lo = fmaxf(lo, fminf(n0, n1)); hi = fminf(hi, fmaxf(n0, n1));
    } else if (A < 0.f || A > 199.f) empty = true;
    if (fabsf(s) > EPS) {
        float n0 = (0.f   - B) / s;
        float n1 = (199.f - B) / s;
        lo = fmaxf(lo, fminf(n0, n1)); hi = fminf(hi, fmaxf(n0, n1));
    } else if (B < 0.f || B > 199.f) empty = true;

    unsigned long long acc01 = 0ull, acc23 = 0ull;
    if (!empty && hi >= lo) {
        int nlo = max(0,    (int)floorf(lo) - 1);
        int nhi = min(NT-1, (int)ceilf (hi) + 1);
        float hc = 0.5f * c, hs = 0.5f * s;
        float Kx = 0.5f * (rns + 199.f);
        float Ky = 0.5f * (rc  + 199.f);

        // trim to the exact valid contiguous interval (same fp formula)
        while (nlo <= nhi) {
            float tn = -350.f + 2.f * (float)nlo;
            float ix = __fmaf_rn(tn, hc, Kx);
            float iy = __fmaf_rn(tn, hs, Ky);
            if (ix >= 0.f && ix <= 199.f && iy >= 0.f && iy <= 199.f) break;
            nlo++;
        }
        while (nhi >= nlo) {
            float tn = -350.f + 2.f * (float)nhi;
            float ix = __fmaf_rn(tn, hc, Kx);
            float iy = __fmaf_rn(tn, hs, Ky);
            if (ix >= 0.f && ix <= 199.f && iy >= 0.f && iy <= 199.f) break;
            nhi--;
        }

        float tn = -350.f + 2.f * (float)nlo;
        #pragma unroll 4
        for (int n = nlo; n <= nhi; n++, tn += 2.f) {
            float ix = __fmaf_rn(tn, hc, Kx);
            float iy = __fmaf_rn(tn, hs, Ky);
            int i0 = (int)ix;
            int j0 = (int)iy;
            float fi = ix - (float)i0;
            float fj = iy - (float)j0;
            float wj = __fmaf_rn(fj, wjs, wjb);
            unsigned base = ((unsigned)(i0*N2 + j0)) << 5;
            const unsigned iofs = (unsigned)(N2*2*N0);            // pad row
            ulonglong2 q0 = *((const ulonglong2*)(st2 + base) + lane8);
            ulonglong2 q1 = *((const ulonglong2*)(st2 + base + iofs) + lane8);
            float w0 = wj * (1.f - fi);
            float w1 = wj * fi;
            unsigned long long w0p = f2_pack(w0, w0);
            unsigned long long w1p = f2_pack(w1, w1);
            f2_fma(acc01, w0p, q0.x);
            f2_fma(acc01, w1p, q1.x);
            f2_fma(acc23, w0p, q0.y);
            f2_fma(acc23, w1p, q1.y);
        }
    }

    acc01 = f2_add(acc01, __shfl_down_sync(0xffffffffu, acc01, 4));
    acc23 = f2_add(acc23, __shfl_down_sync(0xffffffffu, acc23, 4));

    if (live && !isj1) {
        int sidx = ray;
        float2 u01 = f2_unpack(acc01);
        float2 u23 = f2_unpack(acc23);
        float pr[4] = { u01.x*2.f, u01.y*2.f, u23.x*2.f, u23.y*2.f };
        float ov[4];
        #pragma unroll
        for (int k = 0; k < 4; k++) {
            int gi = (zq*4 + k) * NSLOT + sidx;
            float mm = mult[gi];
            float e  = __fmaf_rn(mm, pr[k], contam[gi]);
            ov[k] = mm * data[gi] / e;
        }
        __half2 h01 = __floats2half2_rn(ov[0], ov[1]);
        __half2 h23 = __floats2half2_rn(ov[2], ov[3]);
        uint2 o;
        o.x = *reinterpret_cast<unsigned*>(&h01);
        o.y = *reinterpret_cast<unsigned*>(&h23);
        ((uint2*)zr)[sidx*4 + zq] = o;
    }
}

// ---------------- backprojection (tiled-warp gather, fp16 zr) ---------------
// one thread = (pixel, phi-chunk); warp covers an 8j x 4i pixel tile.
// zr rows are 32B fp16 (2 LDG.128 instead of 4); accumulate stays fp32.
__global__ void __launch_bounds__(256, 5)
k_backproject(const __half* __restrict__ zr, float* __restrict__ bp)
{
    int tid = blockIdx.x * blockDim.x + threadIdx.x;
    if (tid >= NCH * NPIX) return;
    int ch = tid / NPIX;
    int u  = tid % NPIX;                  // NPIX % 32 == 0: warps stay in-chunk
    int lane = u & 31;
    int wu   = u >> 5;                    // 0..1249
    int ti = wu / (N2/8);                 // 0..49  (i tile)
    int tj = wu % (N2/8);                 // 0..24  (j tile)
    int i = ti*4 + (lane >> 3);
    int j = tj*8 + (lane & 7);
    int pix = i * N2 + j;

    float X = -199.f + 2.f * (float)i;
    float Y = -199.f + 2.f * (float)j;

    unsigned long long accp[8];
    #pragma unroll
    for (int k = 0; k < 8; k++) accp[k] = 0ull;

    const float inv_dr = (float)(222.0 / 400.0);
    float cx = 99.5f - (float)i;
    float cy = 99.5f - (float)j;
    float vxl = -(float)i,  vxh = 199.f - (float)i;
    float vyl = -(float)j,  vyh = 199.f - (float)j;
    bool interior = (i >= 1 && i <= N1-2 && j >= 1 && j <= N2-2);

    int plo = ch * CHW;
    int phi_end = min(NPHI, plo + CHW);

    for (int phi = plo; phi < phi_end; phi++) {
        float c = d_COS[phi], s = d_SIN[phi];
        float lim = 2.f * (fabsf(c) + fabsf(s)) + 1e-2f;
        float r0 = -X*s + Y*c;
        float t0 =  X*c + Y*s;
        int mlo = max(0,      (int)ceilf ((r0 + 200.f - lim) * inv_dr));
        int mhi = min(NRAD-1, (int)floorf((r0 + 200.f + lim) * inv_dr));
        int nlo = max(0,      (int)ceilf ((t0 + 350.f - lim) * 0.5f));
        int nhi = min(NT-1,   (int)floorf((t0 + 350.f + lim) * 0.5f));
        int ncnt = nhi - nlo;
        if (ncnt < 0 || mhi < mlo) continue;

        float hc = 0.5f * c, hs = 0.5f * s;
        float tn0 = -350.f + 2.f * (float)nlo;

        for (int m = mlo; m <= mhi; m++) {
            float rm = d_RV[m];
            float Kx = __fmaf_rn(rm, -hs, cx);
            float Ky = __fmaf_rn(rm,  hc, cy);
            float W = 0.f;
            if (interior) {
                float tn = tn0;
                for (int n = 0; n <= ncnt; n++, tn += 2.f) {
                    float dx = __fmaf_rn(tn, hc, Kx);
                    float dy = __fmaf_rn(tn, hs, Ky);
                    float wx = fmaxf(1.f - fabsf(dx), 0.f);
                    float wy = fmaxf(1.f - fabsf(dy), 0.f);
                    W = __fmaf_rn(wx, wy, W);
                }
            } else {
                float tn = tn0;
                for (int n = 0; n <= ncnt; n++, tn += 2.f) {
                    float dx = __fmaf_rn(tn, hc, Kx);
                    float dy = __fmaf_rn(tn, hs, Ky);
                    if (dx < vxl || dx > vxh || dy < vyl || dy > vyh) continue;
                    float wx = fmaxf(1.f - fabsf(dx), 0.f);
                    float wy = fmaxf(1.f - fabsf(dy), 0.f);
                    W = __fmaf_rn(wx, wy, W);
                }
            }
            if (W != 0.f) {
                const uint4* zp = (const uint4*)(zr + (phi*NRAD + m)*N0);
                uint4 a = zp[0], b = zp[1];      // 16 halves = z0..z15
                unsigned long long Wp = f2_pack(W, W);
                f2_fma(accp[0], Wp, h2_to_f2(a.x));
                f2_fma(accp[1], Wp, h2_to_f2(a.y));
                f2_fma(accp[2], Wp, h2_to_f2(a.z));
                f2_fma(accp[3], Wp, h2_to_f2(a.w));
                f2_fma(accp[4], Wp, h2_to_f2(b.x));
                f2_fma(accp[5], Wp, h2_to_f2(b.y));
                f2_fma(accp[6], Wp, h2_to_f2(b.z));
                f2_fma(accp[7], Wp, h2_to_f2(b.w));
            }
        }
    }
    float* dst = bp + ch * NVOX;
    #pragma unroll
    for (int k = 0; k < 8; k++) {
        float2 u2 = f2_unpack(accp[k]);
        dst[(2*k  )*NPIX + pix] = u2.x * 2.f;   // * STEP
        dst[(2*k+1)*NPIX + pix] = u2.y * 2.f;
    }
}

// ---------------- adjoint gauss: fused combine + j-smooth + z-smooth --------
__global__ void k_smooth_jz(const float* __restrict__ bp, float* __restrict__ out)
{
    __shared__ float ta[N0][N2 + 1];
    __shared__ float tj[N0][N2 + 1];
    int i = blockIdx.x;
    // phase 0: combine NCH backprojection partials
    for (int t = threadIdx.x; t < N0*N2; t += blockDim.x) {
        int j = t % N2;
        int z = t / N2;
        const float* base = bp + z*NPIX + i*N2 + j;
        float s = 0.f;
        #pragma unroll
        for (int ch = 0; ch < NCH; ch++)
            s += base[ch*NVOX];
        ta[z][j] = s;
    }
    __syncthreads();
    // phase 1: j-smooth (ta -> tj)
    for (int t = threadIdx.x; t < N0*N2; t += blockDim.x) {
        int j = t % N2;
        int z = t / N2;
        float s = 0.f;
        if (j >= GR && j < N2-GR) {
            #pragma unroll
            for (int d = -GR; d <= GR; d++)
                s += d_GW[d+GR] * ta[z][j+d];
        } else {
            #pragma unroll
            for (int d = -GR; d <= GR; d++)
                s += d_GW[d+GR] * ta[z][refl(j+d, N2)];
        }
        tj[z][j] = s;
    }
    __syncthreads();
    // phase 2: z-smooth -> global
    for (int t = threadIdx.x; t < N0*N2; t += blockDim.x) {
        int j = t % N2;
        int z = t / N2;
        float s = 0.f;
        #pragma unroll
        for (int d = -GR; d <= GR; d++) {
            int m = z + d;
            if (m < 0)   m = -1 - m;
            if (m >= N0) m = 2*N0 - 1 - m;
            s += d_GW[d+GR] * tj[m][j];
        }
        out[z*NPIX + i*N2 + j] = s;
    }
}

// ---------------- adjoint i-smooth + MLEM update -----------------------------
__global__ void k_smooth_i_final(const float* __restrict__ gin,
                                 const float* __restrict__ x,
                                 const float* __restrict__ sens,
                                 float* __restrict__ out)
{
    int t = blockIdx.x * blockDim.x + threadIdx.x;
    if (t >= NVOX) return;
    int j = t % N2;
    int i = (t / N2) % N1;
    int z = t / NPIX;
    const float* base = gin + z*NPIX + j;
    float s = 0.f;
    if (i >= GR && i < N1-GR) {
        #pragma unroll
        for (int d = -GR; d <= GR; d++)
            s += d_GW[d+GR] * base[(i+d) * N2];
    } else {
        #pragma unroll
        for (int d = -GR; d <= GR; d++)
            s += d_GW[d+GR] * base[refl(i+d, N1) * N2];
    }
    out[t] = x[t] * s / sens[t];
}

// ---------------- launch ----------------------------------------------------
extern "C" void kernel_launch(void* const* d_in, const int* in_sizes, int n_in,
                              void* d_out, int out_size)
{
    const float* x      = (const float*)d_in[0];
    const float* data   = (const float*)d_in[1];
    const float* contam = (const float*)d_in[2];
    const float* mult   = (const float*)d_in[3];
    const float* sens   = (const float*)d_in[4];
    float* out = (float*)d_out;

    float *buf1, *st2, *bp;
    __half* zr;
    cudaGetSymbolAddress((void**)&buf1, d_buf1);
    cudaGetSymbolAddress((void**)&st2,  d_st2);
    cudaGetSymbolAddress((void**)&zr,   d_zr);
    cudaGetSymbolAddress((void**)&bp,   d_bp);

    // forward: fused init + gauss3 + paired transposed image
    k_gauss3t2<<<N1, 512>>>(x, st2);

    // project + exp + ratio (fused, fp16 zr out)
    k_project<<<(NSLOT*8 + 255)/256, 256>>>(st2, data, contam, mult, zr);

    // adjoint: backproject (tiled warps, fp16 zr gather), smooths, MLEM
    k_backproject<<<(NCH*NPIX + 255)/256, 256>>>(zr, bp);
    k_smooth_jz<<<N1, 512>>>(bp, buf1);
    k_smooth_i_final<<<(NVOX + 255)/256, 256>>>(buf1, x, sens, out);
}

// round 17
// speedup vs baseline: 1.2891x; 1.0075x over previous
#include <cuda_runtime.h>
#include <cuda_fp16.h>

#define N0 16
#define N1 200
#define N2 200
#define NPIX (N1*N2)          // 40000
#define NVOX (N0*NPIX)        // 640000
#define NPHI 190
#define NRAD 223
#define NT 351
#define GR 4                  // gaussian radius
#define NSLOT (NPHI*NRAD)     // 42370
#define NCH 16                // phi chunks for backprojection
#define CHW 12                // ceil(190/16)

// ---------------- scratch (device globals; no allocation allowed) ----------
__device__ __align__(16) float d_GW[2*GR+1];
__device__ float d_COS[NPHI];
__device__ float d_SIN[NPHI];
__device__ float d_RV[NRAD];
__device__ __align__(16) float d_buf1[NVOX];
__device__ __align__(16) float d_st2[2*NVOX + 2*N0*N2];  // paired img + pad i-row
__device__ __align__(32) __half d_zr[NSLOT*N0];          // fp16 mult*data/exp, [sidx][z]
__device__ __align__(16) unsigned d_bph[NCH*(N0/2)*NPIX]; // fp16x2 bp partials [ch][zpair][pix]

// ---------------- packed f32x2 helpers (Blackwell) --------------------------
__device__ __forceinline__ unsigned long long f2_pack(float a, float b)
{
    unsigned long long r;
    asm("mov.b64 %0, {%1,%2};" : "=l"(r) : "f"(a), "f"(b));
    return r;
}
__device__ __forceinline__ void f2_fma(unsigned long long& d,
                                       unsigned long long a, unsigned long long b)
{
    asm("fma.rn.f32x2 %0, %1, %2, %0;" : "+l"(d) : "l"(a), "l"(b));
}
__device__ __forceinline__ unsigned long long f2_add(unsigned long long a,
                                                     unsigned long long b)
{
    unsigned long long r;
    asm("add.rn.f32x2 %0, %1, %2;" : "=l"(r) : "l"(a), "l"(b));
    return r;
}
__device__ __forceinline__ float2 f2_unpack(unsigned long long v)
{
    float2 r;
    asm("mov.b64 {%0,%1}, %2;" : "=f"(r.x), "=f"(r.y) : "l"(v));
    return r;
}
// half2 word -> packed f32x2 u64
__device__ __forceinline__ unsigned long long h2_to_f2(unsigned h2)
{
    float2 f = __half22float2(*reinterpret_cast<__half2*>(&h2));
    return f2_pack(f.x, f.y);
}

__device__ __forceinline__ int refl(int m, int n)
{
    if (m < 0)  m = -1 - m;
    if (m >= n) m = 2*n - 1 - m;
    return m;
}

// ---------------- fused init + forward gauss3 + paired z-transpose ----------
__global__ void k_gauss3t2(const float* __restrict__ in, float* __restrict__ out2)
{
    __shared__ float ta[N0][N2 + 1];
    __shared__ float tb[N0][N2 + 1];
    __shared__ float sGW[2*GR+1];
    int i = blockIdx.x;

    if (threadIdx.x == 0) {
        const double sigma = 4.5 / (2.35 * 2.0);
        double g[2*GR+1];
        double sum = 0.0;
        for (int k = 0; k <= 2*GR; k++) {
            double dd = (double)(k - GR) / sigma;
            g[k] = exp(-0.5 * dd * dd);
            sum += g[k];
        }
        for (int k = 0; k <= 2*GR; k++) {
            float w = (float)(g[k] / sum);
            sGW[k] = w;
            if (i == 0) d_GW[k] = w;
        }
    }
    if (i == 0) {
        const double PI = 3.14159265358979323846;
        for (int t = threadIdx.x; t < NPHI; t += blockDim.x) {
            float phi = (float)((double)t * (PI / 190.0));
            d_COS[t] = (float)cos((double)phi);
            d_SIN[t] = (float)sin((double)phi);
        }
        for (int t = threadIdx.x; t < NRAD; t += blockDim.x)
            d_RV[t] = (float)(-200.0 + (double)t * (400.0 / 222.0));
    }
    __syncthreads();

    int ridx[2*GR+1];
    #pragma unroll
    for (int d = -GR; d <= GR; d++) ridx[d+GR] = refl(i + d, N1);
    // phase 1: i-smooth
    for (int t = threadIdx.x; t < N0*N2; t += blockDim.x) {
        int j = t % N2;
        int z = t / N2;
        const float* base = in + z*NPIX + j;
        float s = 0.f;
        #pragma unroll
        for (int d = 0; d < 2*GR+1; d++)
            s += sGW[d] * base[ridx[d]*N2];
        ta[z][j] = s;
    }
    __syncthreads();
    // phase 2: j-smooth (ta -> tb)
    for (int t = threadIdx.x; t < N0*N2; t += blockDim.x) {
        int j = t % N2;
        int z = t / N2;
        float s = 0.f;
        if (j >= GR && j < N2-GR) {
            #pragma unroll
            for (int d = -GR; d <= GR; d++)
                s += sGW[d+GR] * ta[z][j+d];
        } else {
            #pragma unroll
            for (int d = -GR; d <= GR; d++)
                s += sGW[d+GR] * ta[z][refl(j+d, N2)];
        }
        tb[z][j] = s;
    }
    __syncthreads();
    // phase 3: z-smooth (tb -> ta)
    for (int t = threadIdx.x; t < N0*N2; t += blockDim.x) {
        int j = t % N2;
        int z = t / N2;
        float s = 0.f;
        #pragma unroll
        for (int d = -GR; d <= GR; d++) {
            int m = z + d;
            if (m < 0)   m = -1 - m;
            if (m >= N0) m = 2*N0 - 1 - m;
            s += sGW[d+GR] * tb[m][j];
        }
        ta[z][j] = s;
    }
    __syncthreads();
    // phase 4: paired-z writes
    for (int t = threadIdx.x; t < N0*N2; t += blockDim.x) {
        int z = t & (N0-1);
        int j = t >> 4;
        int j1 = min(j + 1, N2 - 1);
        float v0 = ta[z][j];
        float v1 = ta[z][j1];
        unsigned base = ((unsigned)(i*N2 + j)) << 5;
        out2[base + z]      = v0;
        out2[base + N0 + z] = v1;
        if (i == N1-1) {   // pad row i = N1 duplicates i = N1-1
            unsigned pbase = ((unsigned)(N1*N2 + j)) << 5;
            out2[pbase + z]      = v0;
            out2[pbase + N0 + z] = v1;
        }
    }
}

// ---------------- forward projection + ratio (fused, fp16 zr out) -----------
__global__ void k_project(const float* __restrict__ st2,
                          const float* __restrict__ data,
                          const float* __restrict__ contam,
                          const float* __restrict__ mult,
                          __half* __restrict__ zr)
{
    int t = blockIdx.x * blockDim.x + threadIdx.x;
    int lane8 = t & 7;
    int ray   = t >> 3;
    bool live = (ray < NSLOT);
    if (!live) ray = NSLOT - 1;           // clamp: keep all 32 lanes for shfl
    int phi = ray / NRAD;
    int rad = ray - phi * NRAD;
    int zq  = lane8 & 3;
    bool isj1 = lane8 >= 4;
    float wjb = isj1 ? 0.f : 1.f;         // wj = fma(fj, wjs, wjb)
    float wjs = isj1 ? 1.f : -1.f;

    float c = d_COS[phi], s = d_SIN[phi];
    float r = d_RV[rad];
    float rns = r * (-s);
    float rc  = r * c;

    float A = 0.5f * (rns + 199.f) - 175.f * c;
    float B = 0.5f * (rc  + 199.f) - 175.f * s;

    const float EPS = 1e-6f;
    float lo = 0.f, hi = 350.f;
    bool empty = false;
    if (fabsf(c) > EPS) {
        float n0 = (0.f   - A) / c;
        float n1 = (199.f - A) / c;
        lo = fmaxf(lo, fminf(n0, n1)); hi = fminf(hi, fmaxf(n0, n1));
    } else if (A < 0.f || A > 199.f) empty = true;
    if (fabsf(s) > EPS) {
        float n0 = (0.f   - B) / s;
        float n1 = (199.f - B) / s;
        lo = fmaxf(lo, fminf(n0, n1)); hi = fminf(hi, fmaxf(n0, n1));
    } else if (B < 0.f || B > 199.f) empty = true;

    unsigned long long acc01 = 0ull, acc23 = 0ull;
    if (!empty && hi >= lo) {
        int nlo = max(0,    (int)floorf(lo) - 1);
        int nhi = min(NT-1, (int)ceilf (hi) + 1);
        float hc = 0.5f * c, hs = 0.5f * s;
        float Kx = 0.5f * (rns + 199.f);
        float Ky = 0.5f * (rc  + 199.f);

        // trim to the exact valid contiguous interval (same fp formula)
        while (nlo <= nhi) {
            float tn = -350.f + 2.f * (float)nlo;
            float ix = __fmaf_rn(tn, hc, Kx);
            float iy = __fmaf_rn(tn, hs, Ky);
            if (ix >= 0.f && ix <= 199.f && iy >= 0.f && iy <= 199.f) break;
            nlo++;
        }
        while (nhi >= nlo) {
            float tn = -350.f + 2.f * (float)nhi;
            float ix = __fmaf_rn(tn, hc, Kx);
            float iy = __fmaf_rn(tn, hs, Ky);
            if (ix >= 0.f && ix <= 199.f && iy >= 0.f && iy <= 199.f) break;
            nhi--;
        }

        float tn = -350.f + 2.f * (float)nlo;
        #pragma unroll 4
        for (int n = nlo; n <= nhi; n++, tn += 2.f) {
            float ix = __fmaf_rn(tn, hc, Kx);
            float iy = __fmaf_rn(tn, hs, Ky);
            int i0 = (int)ix;
            int j0 = (int)iy;
            float fi = ix - (float)i0;
            float fj = iy - (float)j0;
            float wj = __fmaf_rn(fj, wjs, wjb);
            unsigned base = ((unsigned)(i0*N2 + j0)) << 5;
            const unsigned iofs = (unsigned)(N2*2*N0);            // pad row
            ulonglong2 q0 = *((const ulonglong2*)(st2 + base) + lane8);
            ulonglong2 q1 = *((const ulonglong2*)(st2 + base + iofs) + lane8);
            float w0 = wj * (1.f - fi);
            float w1 = wj * fi;
            unsigned long long w0p = f2_pack(w0, w0);
            unsigned long long w1p = f2_pack(w1, w1);
            f2_fma(acc01, w0p, q0.x);
            f2_fma(acc01, w1p, q1.x);
            f2_fma(acc23, w0p, q0.y);
            f2_fma(acc23, w1p, q1.y);
        }
    }

    acc01 = f2_add(acc01, __shfl_down_sync(0xffffffffu, acc01, 4));
    acc23 = f2_add(acc23, __shfl_down_sync(0xffffffffu, acc23, 4));

    if (live && !isj1) {
        int sidx = ray;
        float2 u01 = f2_unpack(acc01);
        float2 u23 = f2_unpack(acc23);
        float pr[4] = { u01.x*2.f, u01.y*2.f, u23.x*2.f, u23.y*2.f };
        float ov[4];
        #pragma unroll
        for (int k = 0; k < 4; k++) {
            int gi = (zq*4 + k) * NSLOT + sidx;
            float mm = mult[gi];
            float e  = __fmaf_rn(mm, pr[k], contam[gi]);
            ov[k] = mm * data[gi] / e;
        }
        __half2 h01 = __floats2half2_rn(ov[0], ov[1]);
        __half2 h23 = __floats2half2_rn(ov[2], ov[3]);
        uint2 o;
        o.x = *reinterpret_cast<unsigned*>(&h01);
        o.y = *reinterpret_cast<unsigned*>(&h23);
        ((uint2*)zr)[sidx*4 + zq] = o;
    }
}

// ---------------- backprojection (tiled-warp gather, fp16 in/out) -----------
// one thread = (pixel, phi-chunk); warp covers an 8j x 4i pixel tile.
// zr rows 32B fp16 (2 LDG.128); partials stored fp16x2 [ch][zpair][pix].
__global__ void __launch_bounds__(256, 5)
k_backproject(const __half* __restrict__ zr, unsigned* __restrict__ bph)
{
    int tid = blockIdx.x * blockDim.x + threadIdx.x;
    if (tid >= NCH * NPIX) return;
    int ch = tid / NPIX;
    int u  = tid % NPIX;                  // NPIX % 32 == 0: warps stay in-chunk
    int lane = u & 31;
    int wu   = u >> 5;                    // 0..1249
    int ti = wu / (N2/8);                 // 0..49  (i tile)
    int tj = wu % (N2/8);                 // 0..24  (j tile)
    int i = ti*4 + (lane >> 3);
    int j = tj*8 + (lane & 7);
    int pix = i * N2 + j;

    float X = -199.f + 2.f * (float)i;
    float Y = -199.f + 2.f * (float)j;

    unsigned long long accp[8];
    #pragma unroll
    for (int k = 0; k < 8; k++) accp[k] = 0ull;

    const float inv_dr = (float)(222.0 / 400.0);
    float cx = 99.5f - (float)i;
    float cy = 99.5f - (float)j;
    float vxl = -(float)i,  vxh = 199.f - (float)i;
    float vyl = -(float)j,  vyh = 199.f - (float)j;
    bool interior = (i >= 1 && i <= N1-2 && j >= 1 && j <= N2-2);

    int plo = ch * CHW;
    int phi_end = min(NPHI, plo + CHW);

    for (int phi = plo; phi < phi_end; phi++) {
        float c = d_COS[phi], s = d_SIN[phi];
        float lim = 2.f * (fabsf(c) + fabsf(s)) + 1e-2f;
        float r0 = -X*s + Y*c;
        float t0 =  X*c + Y*s;
        int mlo = max(0,      (int)ceilf ((r0 + 200.f - lim) * inv_dr));
        int mhi = min(NRAD-1, (int)floorf((r0 + 200.f + lim) * inv_dr));
        int nlo = max(0,      (int)ceilf ((t0 + 350.f - lim) * 0.5f));
        int nhi = min(NT-1,   (int)floorf((t0 + 350.f + lim) * 0.5f));
        int ncnt = nhi - nlo;
        if (ncnt < 0 || mhi < mlo) continue;

        float hc = 0.5f * c, hs = 0.5f * s;
        float tn0 = -350.f + 2.f * (float)nlo;

        for (int m = mlo; m <= mhi; m++) {
            float rm = d_RV[m];
            float Kx = __fmaf_rn(rm, -hs, cx);
            float Ky = __fmaf_rn(rm,  hc, cy);
            float W = 0.f;
            if (interior) {
                float tn = tn0;
                for (int n = 0; n <= ncnt; n++, tn += 2.f) {
                    float dx = __fmaf_rn(tn, hc, Kx);
                    float dy = __fmaf_rn(tn, hs, Ky);
                    float wx = fmaxf(1.f - fabsf(dx), 0.f);
                    float wy = fmaxf(1.f - fabsf(dy), 0.f);
                    W = __fmaf_rn(wx, wy, W);
                }
            } else {
                float tn = tn0;
                for (int n = 0; n <= ncnt; n++, tn += 2.f) {
                    float dx = __fmaf_rn(tn, hc, Kx);
                    float dy = __fmaf_rn(tn, hs, Ky);
                    if (dx < vxl || dx > vxh || dy < vyl || dy > vyh) continue;
                    float wx = fmaxf(1.f - fabsf(dx), 0.f);
                    float wy = fmaxf(1.f - fabsf(dy), 0.f);
                    W = __fmaf_rn(wx, wy, W);
                }
            }
            if (W != 0.f) {
                const uint4* zp = (const uint4*)(zr + (phi*NRAD + m)*N0);
                uint4 a = zp[0], b = zp[1];      // 16 halves = z0..z15
                unsigned long long Wp = f2_pack(W, W);
                f2_fma(accp[0], Wp, h2_to_f2(a.x));
                f2_fma(accp[1], Wp, h2_to_f2(a.y));
                f2_fma(accp[2], Wp, h2_to_f2(a.z));
                f2_fma(accp[3], Wp, h2_to_f2(a.w));
                f2_fma(accp[4], Wp, h2_to_f2(b.x));
                f2_fma(accp[5], Wp, h2_to_f2(b.y));
                f2_fma(accp[6], Wp, h2_to_f2(b.z));
                f2_fma(accp[7], Wp, h2_to_f2(b.w));
            }
        }
    }
    unsigned* dst = bph + ch * (N0/2) * NPIX;
    #pragma unroll
    for (int k = 0; k < 8; k++) {
        float2 u2 = f2_unpack(accp[k]);
        __half2 h = __floats2half2_rn(u2.x * 2.f, u2.y * 2.f);   // * STEP
        dst[k*NPIX + pix] = *reinterpret_cast<unsigned*>(&h);
    }
}

// ---------------- adjoint gauss: fused combine + j-smooth + z-smooth --------
__global__ void k_smooth_jz(const unsigned* __restrict__ bph, float* __restrict__ out)
{
    __shared__ float ta[N0][N2 + 1];
    __shared__ float tj[N0][N2 + 1];
    int i = blockIdx.x;
    // phase 0: combine NCH fp16x2 backprojection partials (fp32 sum)
    for (int t = threadIdx.x; t < (N0/2)*N2; t += blockDim.x) {
        int j = t % N2;
        int k = t / N2;            // z-pair index 0..7
        const unsigned* base = bph + k*NPIX + i*N2 + j;
        float sx = 0.f, sy = 0.f;
        #pragma unroll
        for (int ch = 0; ch < NCH; ch++) {
            unsigned w = base[ch*(N0/2)*NPIX];
            float2 v = __half22float2(*reinterpret_cast<const __half2*>(&w));
            sx += v.x; sy += v.y;
        }
        ta[2*k][j]   = sx;
        ta[2*k+1][j] = sy;
    }
    __syncthreads();
    // phase 1: j-smooth (ta -> tj)
    for (int t = threadIdx.x; t < N0*N2; t += blockDim.x) {
        int j = t % N2;
        int z = t / N2;
        float s = 0.f;
        if (j >= GR && j < N2-GR) {
            #pragma unroll
            for (int d = -GR; d <= GR; d++)
                s += d_GW[d+GR] * ta[z][j+d];
        } else {
            #pragma unroll
            for (int d = -GR; d <= GR; d++)
                s += d_GW[d+GR] * ta[z][refl(j+d, N2)];
        }
        tj[z][j] = s;
    }
    __syncthreads();
    // phase 2: z-smooth -> global
    for (int t = threadIdx.x; t < N0*N2; t += blockDim.x) {
        int j = t % N2;
        int z = t / N2;
        float s = 0.f;
        #pragma unroll
        for (int d = -GR; d <= GR; d++) {
            int m = z + d;
            if (m < 0)   m = -1 - m;
            if (m >= N0) m = 2*N0 - 1 - m;
            s += d_GW[d+GR] * tj[m][j];
        }
        out[z*NPIX + i*N2 + j] = s;
    }
}

// ---------------- adjoint i-smooth + MLEM update -----------------------------
__global__ void k_smooth_i_final(const float* __restrict__ gin,
                                 const float* __restrict__ x,
                                 const float* __restrict__ sens,
                                 float* __restrict__ out)
{
    int t = blockIdx.x * blockDim.x + threadIdx.x;
    if (t >= NVOX) return;
    int j = t % N2;
    int i = (t / N2) % N1;
    int z = t / NPIX;
    const float* base = gin + z*NPIX + j;
    float s = 0.f;
    if (i >= GR && i < N1-GR) {
        #pragma unroll
        for (int d = -GR; d <= GR; d++)
            s += d_GW[d+GR] * base[(i+d) * N2];
    } else {
        #pragma unroll
        for (int d = -GR; d <= GR; d++)
            s += d_GW[d+GR] * base[refl(i+d, N1) * N2];
    }
    out[t] = x[t] * s / sens[t];
}

// ---------------- launch ----------------------------------------------------
extern "C" void kernel_launch(void* const* d_in, const int* in_sizes, int n_in,
                              void* d_out, int out_size)
{
    const float* x      = (const float*)d_in[0];
    const float* data   = (const float*)d_in[1];
    const float* contam = (const float*)d_in[2];
    const float* mult   = (const float*)d_in[3];
    const float* sens   = (const float*)d_in[4];
    float* out = (float*)d_out;

    float *buf1, *st2;
    __half* zr;
    unsigned* bph;
    cudaGetSymbolAddress((void**)&buf1, d_buf1);
    cudaGetSymbolAddress((void**)&st2,  d_st2);
    cudaGetSymbolAddress((void**)&zr,   d_zr);
    cudaGetSymbolAddress((void**)&bph,  d_bph);

    // forward: fused init + gauss3 + paired transposed image
    k_gauss3t2<<<N1, 512>>>(x, st2);

    // project + exp + ratio (fused, fp16 zr out)
    k_project<<<(NSLOT*8 + 255)/256, 256>>>(st2, data, contam, mult, zr);

    // adjoint: backproject (fp16 in/out), smooths, MLEM
    k_backproject<<<(NCH*NPIX + 255)/256, 256>>>(zr, bph);
    k_smooth_jz<<<N1, 512>>>(bph, buf1);
    k_smooth_i_final<<<(NVOX + 255)/256, 256>>>(buf1, x, sens, out);
}